// round 3
// baseline (speedup 1.0000x reference)
#include <cuda_runtime.h>
#include <math.h>

// ---------------- scratch (static device allocations are allowed) ----------
__device__ float g_q[4 * 16 * 4096];     // (b, c16, n)
__device__ float g_k[4 * 16 * 4096];     // (b, c16, n)
__device__ float g_v[4 * 256 * 4096];    // (b, c, n)

// ===========================================================================
// Kernel 1: q = conv1x3(x), k = conv3x1(x)  (raw, bias added; FRN later)
// one block per (b, h) row; 256 threads; ci chunked by 32
// ===========================================================================
__global__ __launch_bounds__(256) void qk_conv_kernel(
    const float* __restrict__ x,
    const float* __restrict__ wq, const float* __restrict__ bq,
    const float* __restrict__ wk, const float* __restrict__ bk)
{
    __shared__ float xs[3 * 32 * 66];   // [dh][ci][w+pad2]
    __shared__ float wqs[16 * 32 * 3];
    __shared__ float wks[16 * 32 * 3];

    int b = blockIdx.x >> 6;
    int h = blockIdx.x & 63;
    int t = threadIdx.x;
    int co = t >> 4;        // 0..15
    int wb = t & 15;        // w base

    float qa[4] = {0.f, 0.f, 0.f, 0.f};
    float ka[4] = {0.f, 0.f, 0.f, 0.f};

    for (int ci0 = 0; ci0 < 256; ci0 += 32) {
        __syncthreads();
        if (t < 96) {                    // zero w-pad columns
            xs[t * 66 + 0]  = 0.f;
            xs[t * 66 + 65] = 0.f;
        }
        for (int idx = t; idx < 3 * 32 * 64; idx += 256) {
            int w  = idx & 63;
            int rc = idx >> 6;           // dh*32+ci
            int dh = rc >> 5;
            int ci = rc & 31;
            int hh = h + dh - 1;
            float v = 0.f;
            if (hh >= 0 && hh < 64)
                v = x[((b * 256 + ci0 + ci) * 64 + hh) * 64 + w];
            xs[rc * 66 + 1 + w] = v;
        }
        for (int idx = t; idx < 16 * 32 * 3; idx += 256) {
            int kk = idx % 3;
            int rc = idx / 3;            // co*32+ci
            int cco = rc >> 5;
            int ci  = rc & 31;
            wqs[idx] = wq[(cco * 256 + ci0 + ci) * 3 + kk];
            wks[idx] = wk[(cco * 256 + ci0 + ci) * 3 + kk];
        }
        __syncthreads();

        for (int ci = 0; ci < 32; ci++) {
            float q0 = wqs[(co * 32 + ci) * 3 + 0];
            float q1 = wqs[(co * 32 + ci) * 3 + 1];
            float q2 = wqs[(co * 32 + ci) * 3 + 2];
            float k0 = wks[(co * 32 + ci) * 3 + 0];
            float k1 = wks[(co * 32 + ci) * 3 + 1];
            float k2 = wks[(co * 32 + ci) * 3 + 2];
            const float* x0 = &xs[(0 * 32 + ci) * 66];
            const float* x1 = &xs[(1 * 32 + ci) * 66];
            const float* x2 = &xs[(2 * 32 + ci) * 66];
#pragma unroll
            for (int r = 0; r < 4; r++) {
                int w = wb + 16 * r;
                float xm = x1[w];        // actual w-1 (padded layout)
                float xc = x1[w + 1];    // actual w
                float xp = x1[w + 2];    // actual w+1
                qa[r] += q0 * xm + q1 * xc + q2 * xp;
                ka[r] += k0 * x0[w + 1] + k1 * xc + k2 * x2[w + 1];
            }
        }
    }
    float bqv = bq[co], bkv = bk[co];
    int base = (b * 16 + co) * 4096 + h * 64;
#pragma unroll
    for (int r = 0; r < 4; r++) {
        int w = wb + 16 * r;
        g_q[base + w] = qa[r] + bqv;
        g_k[base + w] = ka[r] + bkv;
    }
}

// ===========================================================================
// Kernel 2: FRN + Mish in-place on g_q / g_k. One block per (branch,b,c16).
// ===========================================================================
__global__ __launch_bounds__(256) void frn_mish_kernel(
    const float* __restrict__ eps_q, const float* __restrict__ eps_k)
{
    __shared__ float red[256];
    __shared__ float sc_s;
    int id = blockIdx.x;                 // 0..127
    int branch = id >> 6;
    int b = (id >> 4) & 3;
    int c = id & 15;
    float* p = (branch ? g_k : g_q) + (b * 16 + c) * 4096;
    float eps = fabsf(branch ? eps_k[c] : eps_q[c]);
    int t = threadIdx.x;

    float s = 0.f;
    for (int i = t; i < 4096; i += 256) { float v = p[i]; s += v * v; }
    red[t] = s;
    __syncthreads();
    for (int off = 128; off > 0; off >>= 1) {
        if (t < off) red[t] += red[t + off];
        __syncthreads();
    }
    if (t == 0) sc_s = rsqrtf(red[0] / 4096.f + eps);
    __syncthreads();
    float sc = sc_s;
    for (int i = t; i < 4096; i += 256) {
        float v = p[i] * sc;
        float sp = (v > 20.f) ? v : log1pf(expf(v));
        p[i] = v * tanhf(sp);
    }
}

// ===========================================================================
// Kernel 3: v = wv @ x + bv  (1x1 conv as GEMM). 64x64 tiles, 256 threads.
// ===========================================================================
__global__ __launch_bounds__(256) void v_gemm_kernel(
    const float* __restrict__ x,
    const float* __restrict__ wv, const float* __restrict__ bv)
{
    __shared__ float ws[64 * 17];
    __shared__ float xsm[16 * 64];
    int b  = blockIdx.z;
    int c0 = blockIdx.y * 64;
    int n0 = blockIdx.x * 64;
    int t  = threadIdx.x;
    int tx = t & 15, ty = t >> 4;
    float acc[4][4] = {};

    for (int k0 = 0; k0 < 256; k0 += 16) {
        __syncthreads();
        for (int idx = t; idx < 64 * 16; idx += 256) {
            int r = idx >> 4, kk = idx & 15;
            ws[r * 17 + kk] = wv[(c0 + r) * 256 + k0 + kk];
        }
        for (int idx = t; idx < 16 * 64; idx += 256) {
            int kk = idx >> 6, n = idx & 63;
            xsm[kk * 64 + n] = x[(b * 256 + k0 + kk) * 4096 + n0 + n];
        }
        __syncthreads();
#pragma unroll
        for (int kk = 0; kk < 16; kk++) {
            float a[4], bb[4];
#pragma unroll
            for (int i = 0; i < 4; i++) a[i] = ws[(ty + 16 * i) * 17 + kk];
#pragma unroll
            for (int jj = 0; jj < 4; jj++) bb[jj] = xsm[kk * 64 + tx + 16 * jj];
#pragma unroll
            for (int i = 0; i < 4; i++)
#pragma unroll
                for (int jj = 0; jj < 4; jj++)
                    acc[i][jj] += a[i] * bb[jj];
        }
    }
#pragma unroll
    for (int i = 0; i < 4; i++) {
        int c = c0 + ty + 16 * i;
        float bvv = bv[c];
#pragma unroll
        for (int jj = 0; jj < 4; jj++)
            g_v[(b * 256 + c) * 4096 + n0 + tx + 16 * jj] = acc[i][jj] + bvv;
    }
}

// ===========================================================================
// Kernel 4: flash attention + epilogue (gamma * attn + x).
// grid (32, 4) = 128 blocks (single wave), 512 threads, 128 queries/block,
// 64-key tiles. Each warp owns 8 queries; each lane owns channels
// {lane*4..+3, 128+lane*4..+3}; 8x8 fp32 register tile per thread.
// ===========================================================================
#define P_STRIDE 136
#define VS_STRIDE 260
#define ATTN_SMEM_FLOATS (16*128 + 16*64 + 64*P_STRIDE + 64*VS_STRIDE + 128*3 + 512)

__global__ __launch_bounds__(512, 1) void attn_kernel(
    const float* __restrict__ x, const float* __restrict__ gamma,
    float* __restrict__ out)
{
    extern __shared__ float sm[];
    float* Qs   = sm;                        // [c16][128]
    float* Ks   = Qs + 16 * 128;             // [c16][64]
    float* P    = Ks + 16 * 64;              // [n][128] stride 136
    float* Vs   = P + 64 * P_STRIDE;         // [n][256] stride 260
    float* mrow = Vs + 64 * VS_STRIDE;       // [128]
    float* lrow = mrow + 128;
    float* srow = lrow + 128;
    float* red  = srow + 128;                // [4][128]

    int b  = blockIdx.y;
    int j0 = blockIdx.x * 128;
    int t  = threadIdx.x;
    int warp = t >> 5, lane = t & 31;
    int j = t & 127, g = t >> 7;

    const float* qg = g_q + b * 16 * 4096;
    const float* kg = g_k + b * 16 * 4096;
    const float* vg = g_v + b * 256 * 4096;

    for (int i = t; i < 16 * 128; i += 512)
        Qs[i] = qg[(i >> 7) * 4096 + j0 + (i & 127)];
    if (t < 128) { mrow[t] = -1e30f; lrow[t] = 0.f; }

    float O[8][8];
#pragma unroll
    for (int jj = 0; jj < 8; jj++)
#pragma unroll
        for (int cc = 0; cc < 8; cc++) O[jj][cc] = 0.f;

    for (int n0 = 0; n0 < 4096; n0 += 64) {
        __syncthreads();   // protect smem from previous iteration's readers
        for (int i = t; i < 16 * 64; i += 512)
            Ks[i] = kg[(i >> 6) * 4096 + n0 + (i & 63)];
        for (int i4 = t; i4 < 4096; i4 += 512) {   // V transpose: [n][c]
            int c = i4 >> 4, nn = i4 & 15;
            float4 vv = *(const float4*)(vg + c * 4096 + n0 + nn * 4);
            Vs[(nn * 4 + 0) * VS_STRIDE + c] = vv.x;
            Vs[(nn * 4 + 1) * VS_STRIDE + c] = vv.y;
            Vs[(nn * 4 + 2) * VS_STRIDE + c] = vv.z;
            Vs[(nn * 4 + 3) * VS_STRIDE + c] = vv.w;
        }
        __syncthreads();

        // S[n][j] = sum_c Qs[c][j] * Ks[c][n]
#pragma unroll
        for (int i = 0; i < 16; i++) {
            int n = g * 16 + i;
            float s = 0.f;
#pragma unroll
            for (int c = 0; c < 16; c++)
                s += Qs[c * 128 + j] * Ks[c * 64 + n];
            P[n * P_STRIDE + j] = s;
        }
        __syncthreads();

        // online softmax: partial max over this thread's 16 n values
        float pm = -1e30f;
#pragma unroll
        for (int i = 0; i < 16; i++)
            pm = fmaxf(pm, P[(g * 16 + i) * P_STRIDE + j]);
        red[g * 128 + j] = pm;
        __syncthreads();
        if (g == 0) {
            float mnew = fmaxf(fmaxf(red[j], red[128 + j]),
                               fmaxf(red[256 + j], red[384 + j]));
            mnew = fmaxf(mnew, mrow[j]);
            srow[j] = __expf(mrow[j] - mnew);
            mrow[j] = mnew;
        }
        __syncthreads();
        float mn = mrow[j];
        float psum = 0.f;
#pragma unroll
        for (int i = 0; i < 16; i++) {
            int n = g * 16 + i;
            float p = __expf(P[n * P_STRIDE + j] - mn);
            P[n * P_STRIDE + j] = p;
            psum += p;
        }
        red[g * 128 + j] = psum;
        __syncthreads();
        if (g == 0)
            lrow[j] = lrow[j] * srow[j] + red[j] + red[128 + j] + red[256 + j] + red[384 + j];

        // rescale accumulators by exp(m_old - m_new)
#pragma unroll
        for (int jj = 0; jj < 8; jj++) {
            float sc = srow[warp * 8 + jj];
#pragma unroll
            for (int cc = 0; cc < 8; cc++) O[jj][cc] *= sc;
        }

        // PV: O[jj][cc] += P[n][pj+jj] * Vs[n][c]
        int pj = warp * 8;
        int c0 = lane * 4;
        for (int n = 0; n < 64; n++) {
            float4 p0 = *(const float4*)&P[n * P_STRIDE + pj];
            float4 p1 = *(const float4*)&P[n * P_STRIDE + pj + 4];
            float4 v0 = *(const float4*)&Vs[n * VS_STRIDE + c0];
            float4 v1 = *(const float4*)&Vs[n * VS_STRIDE + 128 + c0];
            float pv0 = p0.x, pv1 = p0.y, pv2 = p0.z, pv3 = p0.w;
            float pv4 = p1.x, pv5 = p1.y, pv6 = p1.z, pv7 = p1.w;
            float va[8] = {v0.x, v0.y, v0.z, v0.w, v1.x, v1.y, v1.z, v1.w};
#pragma unroll
            for (int cc = 0; cc < 8; cc++) {
                O[0][cc] += pv0 * va[cc];
                O[1][cc] += pv1 * va[cc];
                O[2][cc] += pv2 * va[cc];
                O[3][cc] += pv3 * va[cc];
                O[4][cc] += pv4 * va[cc];
                O[5][cc] += pv5 * va[cc];
                O[6][cc] += pv6 * va[cc];
                O[7][cc] += pv7 * va[cc];
            }
        }
    }
    __syncthreads();

    // epilogue: out = gamma * (O / l) + x
    float gm = gamma[0];
    int pj = warp * 8;
    int c0 = lane * 4;
#pragma unroll
    for (int jj = 0; jj < 8; jj++) {
        float inv = 1.f / lrow[pj + jj];
        int jg = j0 + pj + jj;
#pragma unroll
        for (int cc = 0; cc < 8; cc++) {
            int c = (cc < 4) ? (c0 + cc) : (128 + c0 + cc - 4);
            int idx = (b * 256 + c) * 4096 + jg;
            out[idx] = gm * (O[jj][cc] * inv) + x[idx];
        }
    }
}

// ===========================================================================
extern "C" void kernel_launch(void* const* d_in, const int* in_sizes, int n_in,
                              void* d_out, int out_size)
{
    const float* x     = (const float*)d_in[0];
    const float* wq    = (const float*)d_in[1];
    const float* bq    = (const float*)d_in[2];
    const float* wk    = (const float*)d_in[3];
    const float* bk    = (const float*)d_in[4];
    const float* wv    = (const float*)d_in[5];
    const float* bv    = (const float*)d_in[6];
    const float* gamma = (const float*)d_in[7];
    const float* eps_q = (const float*)d_in[8];
    const float* eps_k = (const float*)d_in[9];
    float* out = (float*)d_out;

    qk_conv_kernel<<<256, 256>>>(x, wq, bq, wk, bk);
    frn_mish_kernel<<<128, 256>>>(eps_q, eps_k);
    v_gemm_kernel<<<dim3(64, 4, 4), 256>>>(x, wv, bv);

    int smem_bytes = ATTN_SMEM_FLOATS * (int)sizeof(float);
    cudaFuncSetAttribute(attn_kernel,
                         cudaFuncAttributeMaxDynamicSharedMemorySize, smem_bytes);
    attn_kernel<<<dim3(32, 4), 512, smem_bytes>>>(x, gamma, out);
}

// round 6
// speedup vs baseline: 2.5299x; 2.5299x over previous
#include <cuda_runtime.h>
#include <cuda_fp16.h>
#include <math.h>
#include <stdint.h>

// ---------------------------------------------------------------------------
// B=4, C=256, C16=16, H=W=64, N=4096. Attention: 128 q/CTA, 64-key tiles.
// Tile row stride = 72 halves (144B) -> conflict-free per-lane fragment LDS.
// ---------------------------------------------------------------------------

__device__ float g_q[4 * 16 * 4096];             // conv out (b,c16,n) fp32
__device__ float g_k[4 * 16 * 4096];
__device__ __half g_qt[4 * 32 * 128 * 72];       // Q tiles [b][qt][row128][slot72]
__device__ __half g_kt[4 * 64 * 64 * 72];        // K tiles [b][nt][key64][slot72]
__device__ __half g_vt[4 * 64 * 256 * 72];       // V tiles [b][nt][ch256][key72]

// m16n8k16 f16 MMA, fp32 accum (baseline sm_80 PTX -> HMMA on sm_103)
__device__ __forceinline__ void mma16816(float d[4],
    uint32_t a0, uint32_t a1, uint32_t a2, uint32_t a3,
    uint32_t b0, uint32_t b1)
{
    asm volatile(
        "mma.sync.aligned.m16n8k16.row.col.f32.f16.f16.f32 "
        "{%0,%1,%2,%3}, {%4,%5,%6,%7}, {%8,%9}, {%0,%1,%2,%3};"
        : "+f"(d[0]), "+f"(d[1]), "+f"(d[2]), "+f"(d[3])
        : "r"(a0), "r"(a1), "r"(a2), "r"(a3), "r"(b0), "r"(b1));
}
__device__ __forceinline__ uint32_t lds32(const __half* p) {
    return *reinterpret_cast<const uint32_t*>(p);
}

// ===========================================================================
// Kernel 1: q = conv1x3(x), k = conv3x1(x)  (raw + bias, fp32)
// ===========================================================================
__global__ __launch_bounds__(256) void qk_conv_kernel(
    const float* __restrict__ x,
    const float* __restrict__ wq, const float* __restrict__ bq,
    const float* __restrict__ wk, const float* __restrict__ bk)
{
    __shared__ float xs[3 * 32 * 66];
    __shared__ float wqs[16 * 32 * 3];
    __shared__ float wks[16 * 32 * 3];

    int b = blockIdx.x >> 6;
    int h = blockIdx.x & 63;
    int t = threadIdx.x;
    int co = t >> 4;
    int wb = t & 15;

    float qa[4] = {0.f, 0.f, 0.f, 0.f};
    float ka[4] = {0.f, 0.f, 0.f, 0.f};

    for (int ci0 = 0; ci0 < 256; ci0 += 32) {
        __syncthreads();
        if (t < 96) { xs[t * 66 + 0] = 0.f; xs[t * 66 + 65] = 0.f; }
        for (int idx = t; idx < 3 * 32 * 64; idx += 256) {
            int w = idx & 63;
            int rc = idx >> 6;
            int dh = rc >> 5;
            int ci = rc & 31;
            int hh = h + dh - 1;
            float v = 0.f;
            if (hh >= 0 && hh < 64)
                v = x[((b * 256 + ci0 + ci) * 64 + hh) * 64 + w];
            xs[rc * 66 + 1 + w] = v;
        }
        for (int idx = t; idx < 16 * 32 * 3; idx += 256) {
            int kk = idx % 3;
            int rc = idx / 3;
            int cco = rc >> 5;
            int ci = rc & 31;
            wqs[idx] = wq[(cco * 256 + ci0 + ci) * 3 + kk];
            wks[idx] = wk[(cco * 256 + ci0 + ci) * 3 + kk];
        }
        __syncthreads();

        for (int ci = 0; ci < 32; ci++) {
            float q0 = wqs[(co * 32 + ci) * 3 + 0];
            float q1 = wqs[(co * 32 + ci) * 3 + 1];
            float q2 = wqs[(co * 32 + ci) * 3 + 2];
            float k0 = wks[(co * 32 + ci) * 3 + 0];
            float k1 = wks[(co * 32 + ci) * 3 + 1];
            float k2 = wks[(co * 32 + ci) * 3 + 2];
            const float* x0 = &xs[(0 * 32 + ci) * 66];
            const float* x1 = &xs[(1 * 32 + ci) * 66];
            const float* x2 = &xs[(2 * 32 + ci) * 66];
#pragma unroll
            for (int r = 0; r < 4; r++) {
                int w = wb + 16 * r;
                float xm = x1[w];
                float xc = x1[w + 1];
                float xp = x1[w + 2];
                qa[r] += q0 * xm + q1 * xc + q2 * xp;
                ka[r] += k0 * x0[w + 1] + k1 * xc + k2 * x2[w + 1];
            }
        }
    }
    float bqv = bq[co], bkv = bk[co];
    int base = (b * 16 + co) * 4096 + h * 64;
#pragma unroll
    for (int r = 0; r < 4; r++) {
        int w = wb + 16 * r;
        g_q[base + w] = qa[r] + bqv;
        g_k[base + w] = ka[r] + bkv;
    }
}

// ===========================================================================
// Kernel 2: FRN + Mish, then pack f16 hi/lo Q/K tile images.
// Q slots: [c]=hi [16+c]=lo [32+c]=hi ; K slots: [c]=hi [16+c]=hi [32+c]=lo
// => MMA steps give q_hi*k_hi + q_lo*k_hi + q_hi*k_lo ~= fp32 logits.
// ===========================================================================
__global__ __launch_bounds__(256) void frn_mish_pack_kernel(
    const float* __restrict__ eps_q, const float* __restrict__ eps_k)
{
    __shared__ float red[256];
    __shared__ float sc_s;
    int id = blockIdx.x;                 // 0..127
    int branch = id >> 6;
    int b = (id >> 4) & 3;
    int c = id & 15;
    const float* p = (branch ? g_k : g_q) + (b * 16 + c) * 4096;
    float eps = fabsf(branch ? eps_k[c] : eps_q[c]);
    int t = threadIdx.x;

    float s = 0.f;
    for (int i = t; i < 4096; i += 256) { float v = p[i]; s += v * v; }
    red[t] = s;
    __syncthreads();
    for (int off = 128; off > 0; off >>= 1) {
        if (t < off) red[t] += red[t + off];
        __syncthreads();
    }
    if (t == 0) sc_s = rsqrtf(red[0] / 4096.f + eps);
    __syncthreads();
    float sc = sc_s;
    for (int i = t; i < 4096; i += 256) {
        float v = p[i] * sc;
        float sp = (v > 20.f) ? v : log1pf(expf(v));
        float m = v * tanhf(sp);
        __half hi = __float2half_rn(m);
        __half lo = __float2half_rn(m - __half2float(hi));
        if (!branch) {
            int row = i & 127, qt = i >> 7;
            __half* base = g_qt + ((size_t)(b * 32 + qt) * 128 + row) * 72;
            base[c] = hi; base[16 + c] = lo; base[32 + c] = hi;
        } else {
            int key = i & 63, ntl = i >> 6;
            __half* base = g_kt + ((size_t)(b * 64 + ntl) * 64 + key) * 72;
            base[c] = hi; base[16 + c] = hi; base[32 + c] = lo;
        }
    }
}

// ===========================================================================
// Kernel 3: v = wv @ x + bv, f16 into V tile images [b][nt][ch][key(72)].
// ===========================================================================
__global__ __launch_bounds__(256) void v_gemm_kernel(
    const float* __restrict__ x,
    const float* __restrict__ wv, const float* __restrict__ bv)
{
    __shared__ float ws[64 * 17];
    __shared__ float xsm[16 * 64];
    int b  = blockIdx.z;
    int c0 = blockIdx.y * 64;
    int n0 = blockIdx.x * 64;
    int t  = threadIdx.x;
    int tx = t & 15, ty = t >> 4;
    float acc[4][4] = {};

    for (int k0 = 0; k0 < 256; k0 += 16) {
        __syncthreads();
        for (int idx = t; idx < 64 * 16; idx += 256) {
            int r = idx >> 4, kk = idx & 15;
            ws[r * 17 + kk] = wv[(c0 + r) * 256 + k0 + kk];
        }
        for (int idx = t; idx < 16 * 64; idx += 256) {
            int kk = idx >> 6, n = idx & 63;
            xsm[kk * 64 + n] = x[(b * 256 + k0 + kk) * 4096 + n0 + n];
        }
        __syncthreads();
#pragma unroll
        for (int kk = 0; kk < 16; kk++) {
            float a[4], bb[4];
#pragma unroll
            for (int i = 0; i < 4; i++) a[i] = ws[(ty + 16 * i) * 17 + kk];
#pragma unroll
            for (int jj = 0; jj < 4; jj++) bb[jj] = xsm[kk * 64 + tx + 16 * jj];
#pragma unroll
            for (int i = 0; i < 4; i++)
#pragma unroll
                for (int jj = 0; jj < 4; jj++)
                    acc[i][jj] += a[i] * bb[jj];
        }
    }
    int ntl = n0 >> 6;
    __half* vb = g_vt + (size_t)(b * 64 + ntl) * 256 * 72;
#pragma unroll
    for (int i = 0; i < 4; i++) {
        int c = c0 + ty + 16 * i;
        float bvv = bv[c];
#pragma unroll
        for (int jj = 0; jj < 4; jj++) {
            int key = tx + 16 * jj;
            vb[(size_t)c * 72 + key] = __float2half_rn(acc[i][jj] + bvv);
        }
    }
}

// ===========================================================================
// Kernel 4: HMMA flash attention (fixed-max two-pass) + epilogue.
// 512 threads / 16 warps. Warp w: rows 16*(w&7); key-half (pass1) or
// channel-half 128*(w>>3) (PV). Warps 0-7 own softmax + P production.
// ===========================================================================
#define Q_OFF 0
#define K_OFF 9216            // 128*72
#define V_OFF (9216 + 4608)   // + 64*72
#define P_OFF (9216 + 4608 + 18432)  // + 256*72
#define TOT_HALVES (9216 + 4608 + 18432 + 9216)
#define ATTN_SMEM_BYTES (TOT_HALVES * 2 + 384 * 4)

__global__ __launch_bounds__(512, 1) void attn_mma_kernel(
    const float* __restrict__ x, const float* __restrict__ gamma,
    float* __restrict__ out)
{
    extern __shared__ __half sh[];
    __half* Qs = sh + Q_OFF;
    __half* Ks = sh + K_OFF;
    __half* Vs = sh + V_OFF;
    __half* Ps = sh + P_OFF;
    float* s_max  = (float*)(sh + TOT_HALVES);   // [2][128]
    float* s_linv = s_max + 256;                 // [128]

    const int b  = blockIdx.y;
    const int qt = blockIdx.x;
    const int j0 = qt * 128;
    const int t  = threadIdx.x;
    const int w  = t >> 5, lane = t & 31;
    const int gr = lane >> 2, ci = lane & 3;
    const int rw = (w & 7) * 16;                 // row base of this warp
    const int nh = w >> 3;                       // half selector
    const float L2E = 1.44269504f;

    // Q tile load (1152 float4)
    {
        const float4* qg = (const float4*)(g_qt + (size_t)(b * 32 + qt) * 9216);
        float4* qd = (float4*)Qs;
        for (int i = t; i < 1152; i += 512) qd[i] = qg[i];
    }

    // ---------------- pass 1: approx row max (hi*hi step only; softmax is
    // shift-invariant in the per-row constant, so any near-max is exact) ----
    float m0 = -1e30f, m1 = -1e30f;
    for (int ntl = 0; ntl < 64; ntl++) {
        __syncthreads();
        {
            const float4* kg = (const float4*)(g_kt + (size_t)(b * 64 + ntl) * 4608);
            float4* kd = (float4*)Ks;
            for (int i = t; i < 576; i += 512) kd[i] = kg[i];
        }
        __syncthreads();
        uint32_t a0 = lds32(Qs + (rw + gr) * 72 + ci * 2);
        uint32_t a1 = lds32(Qs + (rw + gr + 8) * 72 + ci * 2);
        uint32_t a2 = lds32(Qs + (rw + gr) * 72 + 8 + ci * 2);
        uint32_t a3 = lds32(Qs + (rw + gr + 8) * 72 + 8 + ci * 2);
#pragma unroll
        for (int nb = 0; nb < 4; nb++) {
            int kb = nh * 32 + nb * 8;
            float S[4] = {0.f, 0.f, 0.f, 0.f};
            uint32_t b0 = lds32(Ks + (kb + gr) * 72 + ci * 2);
            uint32_t b1 = lds32(Ks + (kb + gr) * 72 + 8 + ci * 2);
            mma16816(S, a0, a1, a2, a3, b0, b1);
            m0 = fmaxf(m0, fmaxf(S[0], S[1]));
            m1 = fmaxf(m1, fmaxf(S[2], S[3]));
        }
    }
    m0 = fmaxf(m0, __shfl_xor_sync(0xffffffffu, m0, 1));
    m0 = fmaxf(m0, __shfl_xor_sync(0xffffffffu, m0, 2));
    m1 = fmaxf(m1, __shfl_xor_sync(0xffffffffu, m1, 1));
    m1 = fmaxf(m1, __shfl_xor_sync(0xffffffffu, m1, 2));
    if (ci == 0) {
        s_max[nh * 128 + rw + gr]     = m0;
        s_max[nh * 128 + rw + gr + 8] = m1;
    }
    __syncthreads();
    float mL0 = 0.f, mL1 = 0.f;
    if (w < 8) {
        mL0 = fmaxf(s_max[rw + gr],     s_max[128 + rw + gr])     * L2E;
        mL1 = fmaxf(s_max[rw + gr + 8], s_max[128 + rw + gr + 8]) * L2E;
    }

    // ---------------- pass 2: P = exp2(S*log2e - mL), O += P @ V ----------
    float O[16][4];
#pragma unroll
    for (int nb = 0; nb < 16; nb++) { O[nb][0] = O[nb][1] = O[nb][2] = O[nb][3] = 0.f; }
    float l0 = 0.f, l1 = 0.f;

    for (int ntl = 0; ntl < 64; ntl++) {
        __syncthreads();
        {
            const float4* kg = (const float4*)(g_kt + (size_t)(b * 64 + ntl) * 4608);
            float4* kd = (float4*)Ks;
            for (int i = t; i < 576; i += 512) kd[i] = kg[i];
            const float4* vg = (const float4*)(g_vt + (size_t)(b * 64 + ntl) * 18432);
            float4* vd = (float4*)Vs;
            for (int i = t; i < 2304; i += 512) vd[i] = vg[i];
        }
        __syncthreads();
        if (w < 8) {
            float S[8][4];
#pragma unroll
            for (int nb = 0; nb < 8; nb++) { S[nb][0] = S[nb][1] = S[nb][2] = S[nb][3] = 0.f; }
#pragma unroll
            for (int s = 0; s < 3; s++) {
                uint32_t a0 = lds32(Qs + (rw + gr) * 72 + s * 16 + ci * 2);
                uint32_t a1 = lds32(Qs + (rw + gr + 8) * 72 + s * 16 + ci * 2);
                uint32_t a2 = lds32(Qs + (rw + gr) * 72 + s * 16 + 8 + ci * 2);
                uint32_t a3 = lds32(Qs + (rw + gr + 8) * 72 + s * 16 + 8 + ci * 2);
#pragma unroll
                for (int nb = 0; nb < 8; nb++) {
                    uint32_t b0 = lds32(Ks + (nb * 8 + gr) * 72 + s * 16 + ci * 2);
                    uint32_t b1 = lds32(Ks + (nb * 8 + gr) * 72 + s * 16 + 8 + ci * 2);
                    mma16816(S[nb], a0, a1, a2, a3, b0, b1);
                }
            }
            __half2 acc0 = __float2half2_rn(0.f), acc1 = __float2half2_rn(0.f);
#pragma unroll
            for (int nb = 0; nb < 8; nb++) {
                float y0 = fmaf(S[nb][0], L2E, -mL0);
                float y1 = fmaf(S[nb][1], L2E, -mL0);
                float y2 = fmaf(S[nb][2], L2E, -mL1);
                float y3 = fmaf(S[nb][3], L2E, -mL1);
                __half2 h0 = h2exp2(__floats2half2_rn(y0, y1));
                __half2 h1 = h2exp2(__floats2half2_rn(y2, y3));
                *reinterpret_cast<uint32_t*>(Ps + (rw + gr) * 72 + nb * 8 + ci * 2) =
                    *reinterpret_cast<uint32_t*>(&h0);
                *reinterpret_cast<uint32_t*>(Ps + (rw + gr + 8) * 72 + nb * 8 + ci * 2) =
                    *reinterpret_cast<uint32_t*>(&h1);
                acc0 = __hadd2(acc0, h0);
                acc1 = __hadd2(acc1, h1);
            }
            l0 += __low2float(acc0) + __high2float(acc0);
            l1 += __low2float(acc1) + __high2float(acc1);
        }
        __syncthreads();
        // PV: rows rw, channels nh*128 .. +127
#pragma unroll
        for (int s = 0; s < 4; s++) {
            uint32_t a0 = lds32(Ps + (rw + gr) * 72 + s * 16 + ci * 2);
            uint32_t a1 = lds32(Ps + (rw + gr + 8) * 72 + s * 16 + ci * 2);
            uint32_t a2 = lds32(Ps + (rw + gr) * 72 + s * 16 + 8 + ci * 2);
            uint32_t a3 = lds32(Ps + (rw + gr + 8) * 72 + s * 16 + 8 + ci * 2);
#pragma unroll
            for (int nb = 0; nb < 16; nb++) {
                int ch = nh * 128 + nb * 8;
                uint32_t b0 = lds32(Vs + (ch + gr) * 72 + s * 16 + ci * 2);
                uint32_t b1 = lds32(Vs + (ch + gr) * 72 + s * 16 + 8 + ci * 2);
                mma16816(O[nb], a0, a1, a2, a3, b0, b1);
            }
        }
    }

    // l reduction -> 1/l
    if (w < 8) {
        l0 += __shfl_xor_sync(0xffffffffu, l0, 1);
        l0 += __shfl_xor_sync(0xffffffffu, l0, 2);
        l1 += __shfl_xor_sync(0xffffffffu, l1, 1);
        l1 += __shfl_xor_sync(0xffffffffu, l1, 2);
        if (ci == 0) {
            s_linv[rw + gr]     = 1.f / l0;
            s_linv[rw + gr + 8] = 1.f / l1;
        }
    }
    __syncthreads();

    // epilogue: out = gamma*O/l + x
    const float gm = gamma[0];
    const float li0 = s_linv[rw + gr] * gm;
    const float li1 = s_linv[rw + gr + 8] * gm;
    const int r0 = j0 + rw + gr;
#pragma unroll
    for (int nb = 0; nb < 16; nb++) {
        int ch = nh * 128 + nb * 8 + ci * 2;
        size_t i0 = ((size_t)(b * 256 + ch)) * 4096 + r0;
        out[i0]            = O[nb][0] * li0 + x[i0];
        out[i0 + 4096]     = O[nb][1] * li0 + x[i0 + 4096];
        out[i0 + 8]        = O[nb][2] * li1 + x[i0 + 8];
        out[i0 + 4096 + 8] = O[nb][3] * li1 + x[i0 + 4096 + 8];
    }
}

// ===========================================================================
extern "C" void kernel_launch(void* const* d_in, const int* in_sizes, int n_in,
                              void* d_out, int out_size)
{
    const float* x     = (const float*)d_in[0];
    const float* wq    = (const float*)d_in[1];
    const float* bq    = (const float*)d_in[2];
    const float* wk    = (const float*)d_in[3];
    const float* bk    = (const float*)d_in[4];
    const float* wv    = (const float*)d_in[5];
    const float* bv    = (const float*)d_in[6];
    const float* gamma = (const float*)d_in[7];
    const float* eps_q = (const float*)d_in[8];
    const float* eps_k = (const float*)d_in[9];
    float* out = (float*)d_out;

    qk_conv_kernel<<<256, 256>>>(x, wq, bq, wk, bk);
    frn_mish_pack_kernel<<<128, 256>>>(eps_q, eps_k);
    v_gemm_kernel<<<dim3(64, 4, 4), 256>>>(x, wv, bv);

    cudaFuncSetAttribute(attn_mma_kernel,
                         cudaFuncAttributeMaxDynamicSharedMemorySize,
                         ATTN_SMEM_BYTES);
    attn_mma_kernel<<<dim3(32, 4), 512, ATTN_SMEM_BYTES>>>(x, gamma, out);
}

// round 8
// speedup vs baseline: 3.4707x; 1.3719x over previous
#include <cuda_runtime.h>
#include <cuda_fp16.h>
#include <math.h>
#include <stdint.h>

// ---------------------------------------------------------------------------
// B=4, C=256, C16=16, H=W=64, N=4096. Attention: 128 q/CTA, 64-key tiles.
// Tile row stride = 72 halves (144B) -> conflict-free per-lane fragment LDS.
// ---------------------------------------------------------------------------

__device__ float g_q[4 * 16 * 4096];             // conv out (b,c16,n) fp32
__device__ float g_k[4 * 16 * 4096];
__device__ __half g_qt[4 * 32 * 128 * 72];       // Q tiles [b][qt][row128][slot72]
__device__ __half g_kt[4 * 64 * 64 * 72];        // K tiles [b][nt][key64][slot72]
__device__ __half g_vt[4 * 64 * 256 * 72];       // V tiles [b][nt][ch256][key72]

// m16n8k16 f16 MMA, fp32 accum (baseline sm_80 PTX -> HMMA on sm_103)
__device__ __forceinline__ void mma16816(float d[4],
    uint32_t a0, uint32_t a1, uint32_t a2, uint32_t a3,
    uint32_t b0, uint32_t b1)
{
    asm volatile(
        "mma.sync.aligned.m16n8k16.row.col.f32.f16.f16.f32 "
        "{%0,%1,%2,%3}, {%4,%5,%6,%7}, {%8,%9}, {%0,%1,%2,%3};"
        : "+f"(d[0]), "+f"(d[1]), "+f"(d[2]), "+f"(d[3])
        : "r"(a0), "r"(a1), "r"(a2), "r"(a3), "r"(b0), "r"(b1));
}
__device__ __forceinline__ uint32_t lds32(const __half* p) {
    return *reinterpret_cast<const uint32_t*>(p);
}
__device__ __forceinline__ uint32_t smem_u32(const void* p) {
    uint32_t a;
    asm("{ .reg .u64 t; cvta.to.shared.u64 t, %1; cvt.u32.u64 %0, t; }"
        : "=r"(a) : "l"(p));
    return a;
}
__device__ __forceinline__ void cp_async16(uint32_t sm, const void* g) {
    asm volatile("cp.async.cg.shared.global [%0], [%1], 16;"
                 :: "r"(sm), "l"(g) : "memory");
}
#define CP_COMMIT() asm volatile("cp.async.commit_group;" ::: "memory")
#define CP_WAIT0()  asm volatile("cp.async.wait_group 0;" ::: "memory")

// ===========================================================================
// Kernel 1: q = conv1x3(x), k = conv3x1(x)  (raw + bias, fp32)
// ===========================================================================
__global__ __launch_bounds__(256) void qk_conv_kernel(
    const float* __restrict__ x,
    const float* __restrict__ wq, const float* __restrict__ bq,
    const float* __restrict__ wk, const float* __restrict__ bk)
{
    __shared__ float xs[3 * 32 * 66];
    __shared__ float wqs[16 * 32 * 3];
    __shared__ float wks[16 * 32 * 3];

    int b = blockIdx.x >> 6;
    int h = blockIdx.x & 63;
    int t = threadIdx.x;
    int co = t >> 4;
    int wb = t & 15;

    float qa[4] = {0.f, 0.f, 0.f, 0.f};
    float ka[4] = {0.f, 0.f, 0.f, 0.f};

    for (int ci0 = 0; ci0 < 256; ci0 += 32) {
        __syncthreads();
        if (t < 96) { xs[t * 66 + 0] = 0.f; xs[t * 66 + 65] = 0.f; }
        for (int idx = t; idx < 3 * 32 * 64; idx += 256) {
            int w = idx & 63;
            int rc = idx >> 6;
            int dh = rc >> 5;
            int ci = rc & 31;
            int hh = h + dh - 1;
            float v = 0.f;
            if (hh >= 0 && hh < 64)
                v = x[((b * 256 + ci0 + ci) * 64 + hh) * 64 + w];
            xs[rc * 66 + 1 + w] = v;
        }
        for (int idx = t; idx < 16 * 32 * 3; idx += 256) {
            int kk = idx % 3;
            int rc = idx / 3;
            int cco = rc >> 5;
            int ci = rc & 31;
            wqs[idx] = wq[(cco * 256 + ci0 + ci) * 3 + kk];
            wks[idx] = wk[(cco * 256 + ci0 + ci) * 3 + kk];
        }
        __syncthreads();

        for (int ci = 0; ci < 32; ci++) {
            float q0 = wqs[(co * 32 + ci) * 3 + 0];
            float q1 = wqs[(co * 32 + ci) * 3 + 1];
            float q2 = wqs[(co * 32 + ci) * 3 + 2];
            float k0 = wks[(co * 32 + ci) * 3 + 0];
            float k1 = wks[(co * 32 + ci) * 3 + 1];
            float k2 = wks[(co * 32 + ci) * 3 + 2];
            const float* x0 = &xs[(0 * 32 + ci) * 66];
            const float* x1 = &xs[(1 * 32 + ci) * 66];
            const float* x2 = &xs[(2 * 32 + ci) * 66];
#pragma unroll
            for (int r = 0; r < 4; r++) {
                int w = wb + 16 * r;
                float xm = x1[w];
                float xc = x1[w + 1];
                float xp = x1[w + 2];
                qa[r] += q0 * xm + q1 * xc + q2 * xp;
                ka[r] += k0 * x0[w + 1] + k1 * xc + k2 * x2[w + 1];
            }
        }
    }
    float bqv = bq[co], bkv = bk[co];
    int base = (b * 16 + co) * 4096 + h * 64;
#pragma unroll
    for (int r = 0; r < 4; r++) {
        int w = wb + 16 * r;
        g_q[base + w] = qa[r] + bqv;
        g_k[base + w] = ka[r] + bkv;
    }
}

// ===========================================================================
// Kernel 2: FRN + Mish, then pack f16 hi/lo Q/K tile images.
// Q slots: [c]=hi [16+c]=lo [32+c]=hi ; K slots: [c]=hi [16+c]=hi [32+c]=lo
// ===========================================================================
__global__ __launch_bounds__(256) void frn_mish_pack_kernel(
    const float* __restrict__ eps_q, const float* __restrict__ eps_k)
{
    __shared__ float red[256];
    __shared__ float sc_s;
    int id = blockIdx.x;                 // 0..127
    int branch = id >> 6;
    int b = (id >> 4) & 3;
    int c = id & 15;
    const float* p = (branch ? g_k : g_q) + (b * 16 + c) * 4096;
    float eps = fabsf(branch ? eps_k[c] : eps_q[c]);
    int t = threadIdx.x;

    float s = 0.f;
    for (int i = t; i < 4096; i += 256) { float v = p[i]; s += v * v; }
    red[t] = s;
    __syncthreads();
    for (int off = 128; off > 0; off >>= 1) {
        if (t < off) red[t] += red[t + off];
        __syncthreads();
    }
    if (t == 0) sc_s = rsqrtf(red[0] / 4096.f + eps);
    __syncthreads();
    float sc = sc_s;
    for (int i = t; i < 4096; i += 256) {
        float v = p[i] * sc;
        float sp = (v > 20.f) ? v : log1pf(expf(v));
        float m = v * tanhf(sp);
        __half hi = __float2half_rn(m);
        __half lo = __float2half_rn(m - __half2float(hi));
        if (!branch) {
            int row = i & 127, qt = i >> 7;
            __half* base = g_qt + ((size_t)(b * 32 + qt) * 128 + row) * 72;
            base[c] = hi; base[16 + c] = lo; base[32 + c] = hi;
        } else {
            int key = i & 63, ntl = i >> 6;
            __half* base = g_kt + ((size_t)(b * 64 + ntl) * 64 + key) * 72;
            base[c] = hi; base[16 + c] = hi; base[32 + c] = lo;
        }
    }
}

// ===========================================================================
// Kernel 3: v = wv @ x + bv, f16 into V tile images [b][nt][ch][key(72)].
// ===========================================================================
__global__ __launch_bounds__(256) void v_gemm_kernel(
    const float* __restrict__ x,
    const float* __restrict__ wv, const float* __restrict__ bv)
{
    __shared__ float ws[64 * 17];
    __shared__ float xsm[16 * 64];
    int b  = blockIdx.z;
    int c0 = blockIdx.y * 64;
    int n0 = blockIdx.x * 64;
    int t  = threadIdx.x;
    int tx = t & 15, ty = t >> 4;
    float acc[4][4] = {};

    for (int k0 = 0; k0 < 256; k0 += 16) {
        __syncthreads();
        for (int idx = t; idx < 64 * 16; idx += 256) {
            int r = idx >> 4, kk = idx & 15;
            ws[r * 17 + kk] = wv[(c0 + r) * 256 + k0 + kk];
        }
        for (int idx = t; idx < 16 * 64; idx += 256) {
            int kk = idx >> 6, n = idx & 63;
            xsm[kk * 64 + n] = x[(b * 256 + k0 + kk) * 4096 + n0 + n];
        }
        __syncthreads();
#pragma unroll
        for (int kk = 0; kk < 16; kk++) {
            float a[4], bb[4];
#pragma unroll
            for (int i = 0; i < 4; i++) a[i] = ws[(ty + 16 * i) * 17 + kk];
#pragma unroll
            for (int jj = 0; jj < 4; jj++) bb[jj] = xsm[kk * 64 + tx + 16 * jj];
#pragma unroll
            for (int i = 0; i < 4; i++)
#pragma unroll
                for (int jj = 0; jj < 4; jj++)
                    acc[i][jj] += a[i] * bb[jj];
        }
    }
    int ntl = n0 >> 6;
    __half* vb = g_vt + (size_t)(b * 64 + ntl) * 256 * 72;
#pragma unroll
    for (int i = 0; i < 4; i++) {
        int c = c0 + ty + 16 * i;
        float bvv = bv[c];
#pragma unroll
        for (int jj = 0; jj < 4; jj++) {
            int key = tx + 16 * jj;
            vb[(size_t)c * 72 + key] = __float2half_rn(acc[i][jj] + bvv);
        }
    }
}

// ===========================================================================
// Kernel 4: single-pass online-softmax HMMA flash attention + epilogue.
// 512 threads / 16 warps. QK: warp w -> rows 16*(w&7), keys 32*(w>>3).
// PV: warp w -> rows 16*(w&7), channels 128*(w>>3).
// cp.async double-buffered K+V tiles.
// smem halves: Q[0,9216) K2[9216,18432) V2[18432,55296) P[55296,64512)
// ===========================================================================
#define SM_Q 0
#define SM_K(buf) (9216 + (buf) * 4608)
#define SM_V(buf) (18432 + (buf) * 18432)
#define SM_P 55296
#define TOT_HALVES 64512
#define ATTN_SMEM_BYTES (TOT_HALVES * 2 + 512 * 4)

__global__ __launch_bounds__(512, 1) void attn_mma_kernel(
    const float* __restrict__ x, const float* __restrict__ gamma,
    float* __restrict__ out)
{
    extern __shared__ __half sh[];
    __half* Qs = sh + SM_Q;
    __half* Ps = sh + SM_P;
    float* s_pmax = (float*)(sh + TOT_HALVES);   // [2][128]
    float* s_lsum = s_pmax + 256;                // [2][128]

    const int b  = blockIdx.y;
    const int qt = blockIdx.x;
    const int j0 = qt * 128;
    const int t  = threadIdx.x;
    const int w  = t >> 5, lane = t & 31;
    const int gr = lane >> 2, ci = lane & 3;
    const int rw = (w & 7) * 16;                 // row base of this warp
    const int nh = w >> 3;                       // key-half (QK) / ch-half (PV)
    const int kb = nh * 32;                      // QK key base
    const float L2E = 1.44269504f;
    const uint32_t shb = smem_u32(sh);

    // prefetch tile 0
    {
        const float4* kg = (const float4*)(g_kt + (size_t)(b * 64 + 0) * 4608);
        const float4* vg = (const float4*)(g_vt + (size_t)(b * 64 + 0) * 18432);
        uint32_t kd = shb + SM_K(0) * 2;
        uint32_t vd = shb + SM_V(0) * 2;
        for (int i = t; i < 576; i += 512)  cp_async16(kd + i * 16, kg + i);
        for (int i = t; i < 2304; i += 512) cp_async16(vd + i * 16, vg + i);
        CP_COMMIT();
    }
    // Q tile load (1152 float4)
    {
        const float4* qg = (const float4*)(g_qt + (size_t)(b * 32 + qt) * 9216);
        float4* qd = (float4*)Qs;
        for (int i = t; i < 1152; i += 512) qd[i] = qg[i];
    }

    float O[16][4];
#pragma unroll
    for (int nb = 0; nb < 16; nb++) { O[nb][0] = O[nb][1] = O[nb][2] = O[nb][3] = 0.f; }
    float m0 = -1e30f, m1 = -1e30f;
    float l0 = 0.f, l1 = 0.f;

    for (int ntl = 0; ntl < 64; ntl++) {
        CP_WAIT0();
        __syncthreads();

        if (ntl + 1 < 64) {   // prefetch next tile into the other buffer
            int nn = ntl + 1, bf = nn & 1;
            const float4* kg = (const float4*)(g_kt + (size_t)(b * 64 + nn) * 4608);
            const float4* vg = (const float4*)(g_vt + (size_t)(b * 64 + nn) * 18432);
            uint32_t kd = shb + SM_K(bf) * 2;
            uint32_t vd = shb + SM_V(bf) * 2;
            for (int i = t; i < 576; i += 512)  cp_async16(kd + i * 16, kg + i);
            for (int i = t; i < 2304; i += 512) cp_async16(vd + i * 16, vg + i);
            CP_COMMIT();
        }

        const __half* Ks = sh + SM_K(ntl & 1);
        const __half* Vs = sh + SM_V(ntl & 1);

        // ---- QK: 16 rows x 32 keys, hi/lo 3-step ----
        float S[4][4];
#pragma unroll
        for (int nb = 0; nb < 4; nb++) { S[nb][0] = S[nb][1] = S[nb][2] = S[nb][3] = 0.f; }
#pragma unroll
        for (int s = 0; s < 3; s++) {
            uint32_t a0 = lds32(Qs + (rw + gr) * 72 + s * 16 + ci * 2);
            uint32_t a1 = lds32(Qs + (rw + gr + 8) * 72 + s * 16 + ci * 2);
            uint32_t a2 = lds32(Qs + (rw + gr) * 72 + s * 16 + 8 + ci * 2);
            uint32_t a3 = lds32(Qs + (rw + gr + 8) * 72 + s * 16 + 8 + ci * 2);
#pragma unroll
            for (int nb = 0; nb < 4; nb++) {
                uint32_t b0 = lds32(Ks + (kb + nb * 8 + gr) * 72 + s * 16 + ci * 2);
                uint32_t b1 = lds32(Ks + (kb + nb * 8 + gr) * 72 + s * 16 + 8 + ci * 2);
                mma16816(S[nb], a0, a1, a2, a3, b0, b1);
            }
        }
        // partial row max over this warp's 32 keys
        float pm0 = -1e30f, pm1 = -1e30f;
#pragma unroll
        for (int nb = 0; nb < 4; nb++) {
            pm0 = fmaxf(pm0, fmaxf(S[nb][0], S[nb][1]));
            pm1 = fmaxf(pm1, fmaxf(S[nb][2], S[nb][3]));
        }
        pm0 = fmaxf(pm0, __shfl_xor_sync(0xffffffffu, pm0, 1));
        pm0 = fmaxf(pm0, __shfl_xor_sync(0xffffffffu, pm0, 2));
        pm1 = fmaxf(pm1, __shfl_xor_sync(0xffffffffu, pm1, 1));
        pm1 = fmaxf(pm1, __shfl_xor_sync(0xffffffffu, pm1, 2));
        if (ci == 0) {
            s_pmax[nh * 128 + rw + gr]     = pm0;
            s_pmax[nh * 128 + rw + gr + 8] = pm1;
        }
        __syncthreads();

        // ---- combined max, exp -> P, l update, O rescale ----
        float mn0 = fmaxf(m0, fmaxf(s_pmax[rw + gr],     s_pmax[128 + rw + gr]));
        float mn1 = fmaxf(m1, fmaxf(s_pmax[rw + gr + 8], s_pmax[128 + rw + gr + 8]));
        float sc0 = exp2f((m0 - mn0) * L2E);
        float sc1 = exp2f((m1 - mn1) * L2E);
        m0 = mn0; m1 = mn1;
        float nm0 = mn0 * L2E, nm1 = mn1 * L2E;
        float rs0 = 0.f, rs1 = 0.f;
#pragma unroll
        for (int nb = 0; nb < 4; nb++) {
            float y0 = fmaf(S[nb][0], L2E, -nm0);
            float y1 = fmaf(S[nb][1], L2E, -nm0);
            float y2 = fmaf(S[nb][2], L2E, -nm1);
            float y3 = fmaf(S[nb][3], L2E, -nm1);
            float p0 = exp2f(y0), p1 = exp2f(y1);
            float p2 = exp2f(y2), p3 = exp2f(y3);
            rs0 += p0 + p1;
            rs1 += p2 + p3;
            __half2 h0 = __floats2half2_rn(p0, p1);
            __half2 h1 = __floats2half2_rn(p2, p3);
            *reinterpret_cast<uint32_t*>(Ps + (rw + gr) * 72 + kb + nb * 8 + ci * 2) =
                *reinterpret_cast<uint32_t*>(&h0);
            *reinterpret_cast<uint32_t*>(Ps + (rw + gr + 8) * 72 + kb + nb * 8 + ci * 2) =
                *reinterpret_cast<uint32_t*>(&h1);
        }
        rs0 += __shfl_xor_sync(0xffffffffu, rs0, 1);
        rs0 += __shfl_xor_sync(0xffffffffu, rs0, 2);
        rs1 += __shfl_xor_sync(0xffffffffu, rs1, 1);
        rs1 += __shfl_xor_sync(0xffffffffu, rs1, 2);
        l0 = l0 * sc0 + rs0;
        l1 = l1 * sc1 + rs1;
#pragma unroll
        for (int nb = 0; nb < 16; nb++) {
            O[nb][0] *= sc0; O[nb][1] *= sc0;
            O[nb][2] *= sc1; O[nb][3] *= sc1;
        }
        __syncthreads();

        // ---- PV: rows rw, channels nh*128..+127 ----
#pragma unroll
        for (int s = 0; s < 4; s++) {
            uint32_t a0 = lds32(Ps + (rw + gr) * 72 + s * 16 + ci * 2);
            uint32_t a1 = lds32(Ps + (rw + gr + 8) * 72 + s * 16 + ci * 2);
            uint32_t a2 = lds32(Ps + (rw + gr) * 72 + s * 16 + 8 + ci * 2);
            uint32_t a3 = lds32(Ps + (rw + gr + 8) * 72 + s * 16 + 8 + ci * 2);
#pragma unroll
            for (int nb = 0; nb < 16; nb++) {
                int ch = nh * 128 + nb * 8;
                uint32_t b0 = lds32(Vs + (ch + gr) * 72 + s * 16 + ci * 2);
                uint32_t b1 = lds32(Vs + (ch + gr) * 72 + s * 16 + 8 + ci * 2);
                mma16816(O[nb], a0, a1, a2, a3, b0, b1);
            }
        }
    }

    // combine l across the two key-half warps of each row band
    if (ci == 0) {
        s_lsum[nh * 128 + rw + gr]     = l0;
        s_lsum[nh * 128 + rw + gr + 8] = l1;
    }
    __syncthreads();

    // epilogue: out = gamma*O/l + x
    const float gm = gamma[0];
    const float li0 = gm / (s_lsum[rw + gr]     + s_lsum[128 + rw + gr]);
    const float li1 = gm / (s_lsum[rw + gr + 8] + s_lsum[128 + rw + gr + 8]);
    const int r0 = j0 + rw + gr;
#pragma unroll
    for (int nb = 0; nb < 16; nb++) {
        int ch = nh * 128 + nb * 8 + ci * 2;
        size_t i0 = ((size_t)(b * 256 + ch)) * 4096 + r0;
        out[i0]            = O[nb][0] * li0 + x[i0];
        out[i0 + 4096]     = O[nb][1] * li0 + x[i0 + 4096];
        out[i0 + 8]        = O[nb][2] * li1 + x[i0 + 8];
        out[i0 + 4096 + 8] = O[nb][3] * li1 + x[i0 + 4096 + 8];
    }
}

// ===========================================================================
extern "C" void kernel_launch(void* const* d_in, const int* in_sizes, int n_in,
                              void* d_out, int out_size)
{
    const float* x     = (const float*)d_in[0];
    const float* wq    = (const float*)d_in[1];
    const float* bq    = (const float*)d_in[2];
    const float* wk    = (const float*)d_in[3];
    const float* bk    = (const float*)d_in[4];
    const float* wv    = (const float*)d_in[5];
    const float* bv    = (const float*)d_in[6];
    const float* gamma = (const float*)d_in[7];
    const float* eps_q = (const float*)d_in[8];
    const float* eps_k = (const float*)d_in[9];
    float* out = (float*)d_out;

    qk_conv_kernel<<<256, 256>>>(x, wq, bq, wk, bk);
    frn_mish_pack_kernel<<<128, 256>>>(eps_q, eps_k);
    v_gemm_kernel<<<dim3(64, 4, 4), 256>>>(x, wv, bv);

    cudaFuncSetAttribute(attn_mma_kernel,
                         cudaFuncAttributeMaxDynamicSharedMemorySize,
                         ATTN_SMEM_BYTES);
    attn_mma_kernel<<<dim3(32, 4), 512, ATTN_SMEM_BYTES>>>(x, gamma, out);
}

// round 10
// speedup vs baseline: 4.4507x; 1.2824x over previous
#include <cuda_runtime.h>
#include <cuda_fp16.h>
#include <math.h>
#include <stdint.h>

// ---------------------------------------------------------------------------
// B=4, C=256, C16=16, H=W=64, N=4096. Attention: 128 q/CTA, 64-key tiles.
// Tile row stride = 72 halves (144B) -> conflict-free LDS32 and LDSM.
// ---------------------------------------------------------------------------

__device__ float g_q[4 * 16 * 4096];             // conv out (b,c16,n) fp32
__device__ float g_k[4 * 16 * 4096];
__device__ __half g_qt[4 * 32 * 128 * 72];       // Q tiles [b][qt][row128][slot72]
__device__ __half g_kt[4 * 64 * 64 * 72];        // K tiles [b][nt][key64][slot72]
__device__ __half g_vt[4 * 64 * 256 * 72];       // V tiles [b][nt][ch256][key72]

// m16n8k16 f16 MMA, fp32 accum (baseline sm_80 PTX -> HMMA on sm_103)
__device__ __forceinline__ void mma16816(float d[4],
    uint32_t a0, uint32_t a1, uint32_t a2, uint32_t a3,
    uint32_t b0, uint32_t b1)
{
    asm volatile(
        "mma.sync.aligned.m16n8k16.row.col.f32.f16.f16.f32 "
        "{%0,%1,%2,%3}, {%4,%5,%6,%7}, {%8,%9}, {%0,%1,%2,%3};"
        : "+f"(d[0]), "+f"(d[1]), "+f"(d[2]), "+f"(d[3])
        : "r"(a0), "r"(a1), "r"(a2), "r"(a3), "r"(b0), "r"(b1));
}
__device__ __forceinline__ void ldsm_x4(uint32_t& r0, uint32_t& r1,
                                        uint32_t& r2, uint32_t& r3, uint32_t a) {
    asm volatile("ldmatrix.sync.aligned.m8n8.x4.shared.b16 {%0,%1,%2,%3}, [%4];"
                 : "=r"(r0), "=r"(r1), "=r"(r2), "=r"(r3) : "r"(a));
}
__device__ __forceinline__ void ldsm_x4_t(uint32_t& r0, uint32_t& r1,
                                          uint32_t& r2, uint32_t& r3, uint32_t a) {
    asm volatile("ldmatrix.sync.aligned.m8n8.x4.trans.shared.b16 {%0,%1,%2,%3}, [%4];"
                 : "=r"(r0), "=r"(r1), "=r"(r2), "=r"(r3) : "r"(a));
}
__device__ __forceinline__ uint32_t smem_u32(const void* p) {
    uint32_t a;
    asm("{ .reg .u64 t; cvta.to.shared.u64 t, %1; cvt.u32.u64 %0, t; }"
        : "=r"(a) : "l"(p));
    return a;
}
__device__ __forceinline__ void cp_async16(uint32_t sm, const void* g) {
    asm volatile("cp.async.cg.shared.global [%0], [%1], 16;"
                 :: "r"(sm), "l"(g) : "memory");
}
#define CP_COMMIT() asm volatile("cp.async.commit_group;" ::: "memory")
#define CP_WAIT0()  asm volatile("cp.async.wait_group 0;" ::: "memory")
#define BAR_PAIR(id) asm volatile("bar.sync %0, 64;" :: "r"(id) : "memory")

// ===========================================================================
// Kernel 1: q = conv1x3(x), k = conv3x1(x)  (raw + bias, fp32)
// ===========================================================================
__global__ __launch_bounds__(256) void qk_conv_kernel(
    const float* __restrict__ x,
    const float* __restrict__ wq, const float* __restrict__ bq,
    const float* __restrict__ wk, const float* __restrict__ bk)
{
    __shared__ float xs[3 * 32 * 66];
    __shared__ float wqs[16 * 32 * 3];
    __shared__ float wks[16 * 32 * 3];

    int b = blockIdx.x >> 6;
    int h = blockIdx.x & 63;
    int t = threadIdx.x;
    int co = t >> 4;
    int wb = t & 15;

    float qa[4] = {0.f, 0.f, 0.f, 0.f};
    float ka[4] = {0.f, 0.f, 0.f, 0.f};

    for (int ci0 = 0; ci0 < 256; ci0 += 32) {
        __syncthreads();
        if (t < 96) { xs[t * 66 + 0] = 0.f; xs[t * 66 + 65] = 0.f; }
        for (int idx = t; idx < 3 * 32 * 64; idx += 256) {
            int w = idx & 63;
            int rc = idx >> 6;
            int dh = rc >> 5;
            int ci = rc & 31;
            int hh = h + dh - 1;
            float v = 0.f;
            if (hh >= 0 && hh < 64)
                v = x[((b * 256 + ci0 + ci) * 64 + hh) * 64 + w];
            xs[rc * 66 + 1 + w] = v;
        }
        for (int idx = t; idx < 16 * 32 * 3; idx += 256) {
            int kk = idx % 3;
            int rc = idx / 3;
            int cco = rc >> 5;
            int ci = rc & 31;
            wqs[idx] = wq[(cco * 256 + ci0 + ci) * 3 + kk];
            wks[idx] = wk[(cco * 256 + ci0 + ci) * 3 + kk];
        }
        __syncthreads();

        for (int ci = 0; ci < 32; ci++) {
            float q0 = wqs[(co * 32 + ci) * 3 + 0];
            float q1 = wqs[(co * 32 + ci) * 3 + 1];
            float q2 = wqs[(co * 32 + ci) * 3 + 2];
            float k0 = wks[(co * 32 + ci) * 3 + 0];
            float k1 = wks[(co * 32 + ci) * 3 + 1];
            float k2 = wks[(co * 32 + ci) * 3 + 2];
            const float* x0 = &xs[(0 * 32 + ci) * 66];
            const float* x1 = &xs[(1 * 32 + ci) * 66];
            const float* x2 = &xs[(2 * 32 + ci) * 66];
#pragma unroll
            for (int r = 0; r < 4; r++) {
                int w = wb + 16 * r;
                float xm = x1[w];
                float xc = x1[w + 1];
                float xp = x1[w + 2];
                qa[r] += q0 * xm + q1 * xc + q2 * xp;
                ka[r] += k0 * x0[w + 1] + k1 * xc + k2 * x2[w + 1];
            }
        }
    }
    float bqv = bq[co], bkv = bk[co];
    int base = (b * 16 + co) * 4096 + h * 64;
#pragma unroll
    for (int r = 0; r < 4; r++) {
        int w = wb + 16 * r;
        g_q[base + w] = qa[r] + bqv;
        g_k[base + w] = ka[r] + bkv;
    }
}

// ===========================================================================
// Kernel 2: FRN + Mish, then pack f16 hi/lo Q/K tile images.
// Q slots: [c]=hi [16+c]=lo [32+c]=hi ; K slots: [c]=hi [16+c]=hi [32+c]=lo
// ===========================================================================
__global__ __launch_bounds__(256) void frn_mish_pack_kernel(
    const float* __restrict__ eps_q, const float* __restrict__ eps_k)
{
    __shared__ float red[256];
    __shared__ float sc_s;
    int id = blockIdx.x;                 // 0..127
    int branch = id >> 6;
    int b = (id >> 4) & 3;
    int c = id & 15;
    const float* p = (branch ? g_k : g_q) + (b * 16 + c) * 4096;
    float eps = fabsf(branch ? eps_k[c] : eps_q[c]);
    int t = threadIdx.x;

    float s = 0.f;
    for (int i = t; i < 4096; i += 256) { float v = p[i]; s += v * v; }
    red[t] = s;
    __syncthreads();
    for (int off = 128; off > 0; off >>= 1) {
        if (t < off) red[t] += red[t + off];
        __syncthreads();
    }
    if (t == 0) sc_s = rsqrtf(red[0] / 4096.f + eps);
    __syncthreads();
    float sc = sc_s;
    for (int i = t; i < 4096; i += 256) {
        float v = p[i] * sc;
        float sp = (v > 20.f) ? v : log1pf(expf(v));
        float m = v * tanhf(sp);
        __half hi = __float2half_rn(m);
        __half lo = __float2half_rn(m - __half2float(hi));
        if (!branch) {
            int row = i & 127, qt = i >> 7;
            __half* base = g_qt + ((size_t)(b * 32 + qt) * 128 + row) * 72;
            base[c] = hi; base[16 + c] = lo; base[32 + c] = hi;
        } else {
            int key = i & 63, ntl = i >> 6;
            __half* base = g_kt + ((size_t)(b * 64 + ntl) * 64 + key) * 72;
            base[c] = hi; base[16 + c] = hi; base[32 + c] = lo;
        }
    }
}

// ===========================================================================
// Kernel 3: v = wv @ x + bv via HMMA (f16 inputs, fp32 accum).
// Grid (32 n-blocks, 4 b), 512 threads / 16 warps. Warp w: 16 channels.
// smem: wv chunk [256][72] f16, x chunk [64][136] f16 (ldmatrix.trans).
// ===========================================================================
#define VG_XOFF (256 * 72)
#define VG_SMEM ((256 * 72 + 64 * 136) * 2)

__global__ __launch_bounds__(512) void v_gemm_mma_kernel(
    const float* __restrict__ x,
    const float* __restrict__ wv, const float* __restrict__ bv)
{
    extern __shared__ __half vsh[];
    __half* Ws = vsh;
    __half* Xs = vsh + VG_XOFF;
    const int b = blockIdx.y, nblk = blockIdx.x, n0 = nblk * 128;
    const int t = threadIdx.x, w = t >> 5, lane = t & 31;
    const int g = lane >> 3, r8 = lane & 7;
    const int cw = w * 16;
    const uint32_t shb = smem_u32(vsh);
    // A fragment lane address (wv): row cw + (g&1)*8 + r8, kofs (g>>1)*8
    const uint32_t aA = shb + ((cw + (g & 1) * 8 + r8) * 72 + (g >> 1) * 8) * 2;
    // B fragment lane address (x, trans): k-row (g&1)*8+r8, ncol (g>>1)*8
    const uint32_t aB = shb + VG_XOFF * 2 + ((g & 1) * 8 + r8) * 136 * 2 + (g >> 1) * 16;

    float Acc[16][4];
#pragma unroll
    for (int nb = 0; nb < 16; nb++)
        Acc[nb][0] = Acc[nb][1] = Acc[nb][2] = Acc[nb][3] = 0.f;

    for (int kc = 0; kc < 4; kc++) {
        __syncthreads();
        // stage wv chunk [256 c][64 k] -> f16
        for (int idx = t; idx < 4096; idx += 512) {
            int row = idx >> 4, col4 = (idx & 15) * 4;
            float4 v = *(const float4*)(wv + row * 256 + kc * 64 + col4);
            uint2 hh;
            __half2 h0 = __floats2half2_rn(v.x, v.y);
            __half2 h1 = __floats2half2_rn(v.z, v.w);
            hh.x = *reinterpret_cast<uint32_t*>(&h0);
            hh.y = *reinterpret_cast<uint32_t*>(&h1);
            *reinterpret_cast<uint2*>(Ws + row * 72 + col4) = hh;
        }
        // stage x chunk [64 k][128 n] -> f16
        for (int idx = t; idx < 2048; idx += 512) {
            int row = idx >> 5, col4 = (idx & 31) * 4;
            float4 v = *(const float4*)(x + (size_t)(b * 256 + kc * 64 + row) * 4096 + n0 + col4);
            uint2 hh;
            __half2 h0 = __floats2half2_rn(v.x, v.y);
            __half2 h1 = __floats2half2_rn(v.z, v.w);
            hh.x = *reinterpret_cast<uint32_t*>(&h0);
            hh.y = *reinterpret_cast<uint32_t*>(&h1);
            *reinterpret_cast<uint2*>(Xs + row * 136 + col4) = hh;
        }
        __syncthreads();
#pragma unroll
        for (int s = 0; s < 4; s++) {
            uint32_t a0, a1, a2, a3;
            ldsm_x4(a0, a1, a2, a3, aA + s * 32);
#pragma unroll
            for (int p = 0; p < 8; p++) {
                uint32_t b0, b1, b2, b3;
                ldsm_x4_t(b0, b1, b2, b3, aB + s * (16 * 136 * 2) + p * 32);
                mma16816(Acc[2 * p], a0, a1, a2, a3, b0, b1);
                mma16816(Acc[2 * p + 1], a0, a1, a2, a3, b2, b3);
            }
        }
    }

    // epilogue: + bv, f16, store to g_vt tile images
    const int c0 = cw + (lane >> 2);
    const float bv0 = bv[c0], bv1 = bv[c0 + 8];
#pragma unroll
    for (int nb = 0; nb < 16; nb++) {
        int nl = nb * 8 + (lane & 3) * 2;       // local n 0..127
        int ntl = nblk * 2 + (nl >> 6);
        int key = nl & 63;
        __half* vb = g_vt + (size_t)(b * 64 + ntl) * 256 * 72;
        __half2 h0 = __floats2half2_rn(Acc[nb][0] + bv0, Acc[nb][1] + bv0);
        __half2 h1 = __floats2half2_rn(Acc[nb][2] + bv1, Acc[nb][3] + bv1);
        *reinterpret_cast<uint32_t*>(vb + (size_t)c0 * 72 + key) =
            *reinterpret_cast<uint32_t*>(&h0);
        *reinterpret_cast<uint32_t*>(vb + (size_t)(c0 + 8) * 72 + key) =
            *reinterpret_cast<uint32_t*>(&h1);
    }
}

// ===========================================================================
// Kernel 4: single-pass online-softmax HMMA flash attention + epilogue.
// 512 threads / 16 warps. QK: warp w -> rows 16*(w&7), keys 32*(w>>3).
// PV: warp w -> rows 16*(w&7), channels 128*(w>>3).
// cp.async double-buffered K+V; ldmatrix fragments; pairwise barriers.
// ===========================================================================
#define SM_Q 0
#define SM_K(buf) (9216 + (buf) * 4608)
#define SM_V(buf) (18432 + (buf) * 18432)
#define SM_P 55296
#define TOT_HALVES 64512
#define ATTN_SMEM_BYTES (TOT_HALVES * 2 + 512 * 4)

__global__ __launch_bounds__(512, 1) void attn_mma_kernel(
    const float* __restrict__ x, const float* __restrict__ gamma,
    float* __restrict__ out)
{
    extern __shared__ __half sh[];
    __half* Qs = sh + SM_Q;
    __half* Ps = sh + SM_P;
    float* s_pmax = (float*)(sh + TOT_HALVES);   // [2][128]
    float* s_lsum = s_pmax + 256;                // [2][128]

    const int b  = blockIdx.y;
    const int qt = blockIdx.x;
    const int j0 = qt * 128;
    const int t  = threadIdx.x;
    const int w  = t >> 5, lane = t & 31;
    const int gr = lane >> 2, ci = lane & 3;
    const int g  = lane >> 3, r8 = lane & 7;
    const int rw = (w & 7) * 16;                 // row base of this warp
    const int nh = w >> 3;                       // key-half (QK) / ch-half (PV)
    const int kb = nh * 32;                      // QK key base
    const int barid = 1 + (w & 7);               // pairwise barrier id
    const float L2E = 1.44269504f;
    const uint32_t shb = smem_u32(sh);

    // LDSM lane addresses (A-style: row rw + (g&1)*8 + r8, kofs (g>>1)*8)
    const uint32_t aQ = shb + SM_Q * 2 + ((rw + (g & 1) * 8 + r8) * 72 + (g >> 1) * 8) * 2;
    const uint32_t aP = shb + SM_P * 2 + ((rw + (g & 1) * 8 + r8) * 72 + (g >> 1) * 8) * 2;
    // B-style (pair of 8-tiles): row base + (g>>1)*8 + r8, kofs (g&1)*8
    const uint32_t oK = ((kb + (g >> 1) * 8 + r8) * 72 + (g & 1) * 8) * 2;
    const uint32_t oV = ((nh * 128 + (g >> 1) * 8 + r8) * 72 + (g & 1) * 8) * 2;

    // prefetch tile 0
    {
        const float4* kg = (const float4*)(g_kt + (size_t)(b * 64 + 0) * 4608);
        const float4* vg = (const float4*)(g_vt + (size_t)(b * 64 + 0) * 18432);
        uint32_t kd = shb + SM_K(0) * 2;
        uint32_t vd = shb + SM_V(0) * 2;
        for (int i = t; i < 576; i += 512)  cp_async16(kd + i * 16, kg + i);
        for (int i = t; i < 2304; i += 512) cp_async16(vd + i * 16, vg + i);
        CP_COMMIT();
    }
    // Q tile load (1152 float4)
    {
        const float4* qg = (const float4*)(g_qt + (size_t)(b * 32 + qt) * 9216);
        float4* qd = (float4*)Qs;
        for (int i = t; i < 1152; i += 512) qd[i] = qg[i];
    }

    float O[16][4];
#pragma unroll
    for (int nb = 0; nb < 16; nb++) { O[nb][0] = O[nb][1] = O[nb][2] = O[nb][3] = 0.f; }
    float m0 = -1e30f, m1 = -1e30f;
    float l0 = 0.f, l1 = 0.f;

    for (int ntl = 0; ntl < 64; ntl++) {
        CP_WAIT0();
        __syncthreads();     // full barrier: tile data arrived + buffers free

        if (ntl + 1 < 64) {  // prefetch next tile into the other buffer
            int nn = ntl + 1, bf = nn & 1;
            const float4* kg = (const float4*)(g_kt + (size_t)(b * 64 + nn) * 4608);
            const float4* vg = (const float4*)(g_vt + (size_t)(b * 64 + nn) * 18432);
            uint32_t kd = shb + SM_K(bf) * 2;
            uint32_t vd = shb + SM_V(bf) * 2;
            for (int i = t; i < 576; i += 512)  cp_async16(kd + i * 16, kg + i);
            for (int i = t; i < 2304; i += 512) cp_async16(vd + i * 16, vg + i);
            CP_COMMIT();
        }

        const uint32_t kbyte = shb + SM_K(ntl & 1) * 2;
        const uint32_t vbyte = shb + SM_V(ntl & 1) * 2;

        // ---- QK: 16 rows x 32 keys, hi/lo 3-step, LDSM fragments ----
        float S[4][4];
#pragma unroll
        for (int nb = 0; nb < 4; nb++) { S[nb][0] = S[nb][1] = S[nb][2] = S[nb][3] = 0.f; }
#pragma unroll
        for (int s = 0; s < 3; s++) {
            uint32_t a0, a1, a2, a3;
            ldsm_x4(a0, a1, a2, a3, aQ + s * 32);
            uint32_t b0, b1, b2, b3;
            ldsm_x4(b0, b1, b2, b3, kbyte + oK + s * 32);
            mma16816(S[0], a0, a1, a2, a3, b0, b1);
            mma16816(S[1], a0, a1, a2, a3, b2, b3);
            ldsm_x4(b0, b1, b2, b3, kbyte + oK + 2304 + s * 32);
            mma16816(S[2], a0, a1, a2, a3, b0, b1);
            mma16816(S[3], a0, a1, a2, a3, b2, b3);
        }
        // partial row max over this warp's 32 keys
        float pm0 = -1e30f, pm1 = -1e30f;
#pragma unroll
        for (int nb = 0; nb < 4; nb++) {
            pm0 = fmaxf(pm0, fmaxf(S[nb][0], S[nb][1]));
            pm1 = fmaxf(pm1, fmaxf(S[nb][2], S[nb][3]));
        }
        pm0 = fmaxf(pm0, __shfl_xor_sync(0xffffffffu, pm0, 1));
        pm0 = fmaxf(pm0, __shfl_xor_sync(0xffffffffu, pm0, 2));
        pm1 = fmaxf(pm1, __shfl_xor_sync(0xffffffffu, pm1, 1));
        pm1 = fmaxf(pm1, __shfl_xor_sync(0xffffffffu, pm1, 2));
        if (ci == 0) {
            s_pmax[nh * 128 + rw + gr]     = pm0;
            s_pmax[nh * 128 + rw + gr + 8] = pm1;
        }
        BAR_PAIR(barid);     // only warps w and w^8 share this row band

        // ---- combined max, exp -> P, l update, O rescale ----
        float mn0 = fmaxf(m0, fmaxf(s_pmax[rw + gr],     s_pmax[128 + rw + gr]));
        float mn1 = fmaxf(m1, fmaxf(s_pmax[rw + gr + 8], s_pmax[128 + rw + gr + 8]));
        float sc0 = exp2f((m0 - mn0) * L2E);
        float sc1 = exp2f((m1 - mn1) * L2E);
        m0 = mn0; m1 = mn1;
        float nm0 = mn0 * L2E, nm1 = mn1 * L2E;
        float rs0 = 0.f, rs1 = 0.f;
#pragma unroll
        for (int nb = 0; nb < 4; nb++) {
            float y0 = fmaf(S[nb][0], L2E, -nm0);
            float y1 = fmaf(S[nb][1], L2E, -nm0);
            float y2 = fmaf(S[nb][2], L2E, -nm1);
            float y3 = fmaf(S[nb][3], L2E, -nm1);
            float p0 = exp2f(y0), p1 = exp2f(y1);
            float p2 = exp2f(y2), p3 = exp2f(y3);
            rs0 += p0 + p1;
            rs1 += p2 + p3;
            __half2 h0 = __floats2half2_rn(p0, p1);
            __half2 h1 = __floats2half2_rn(p2, p3);
            *reinterpret_cast<uint32_t*>(Ps + (rw + gr) * 72 + kb + nb * 8 + ci * 2) =
                *reinterpret_cast<uint32_t*>(&h0);
            *reinterpret_cast<uint32_t*>(Ps + (rw + gr + 8) * 72 + kb + nb * 8 + ci * 2) =
                *reinterpret_cast<uint32_t*>(&h1);
        }
        rs0 += __shfl_xor_sync(0xffffffffu, rs0, 1);
        rs0 += __shfl_xor_sync(0xffffffffu, rs0, 2);
        rs1 += __shfl_xor_sync(0xffffffffu, rs1, 1);
        rs1 += __shfl_xor_sync(0xffffffffu, rs1, 2);
        l0 = l0 * sc0 + rs0;
        l1 = l1 * sc1 + rs1;
#pragma unroll
        for (int nb = 0; nb < 16; nb++) {
            O[nb][0] *= sc0; O[nb][1] *= sc0;
            O[nb][2] *= sc1; O[nb][3] *= sc1;
        }
        BAR_PAIR(barid);     // partner's P half visible

        // ---- PV: rows rw, channels nh*128..+127 (LDSM fragments) ----
#pragma unroll
        for (int s = 0; s < 4; s++) {
            uint32_t a0, a1, a2, a3;
            ldsm_x4(a0, a1, a2, a3, aP + s * 32);
#pragma unroll
            for (int p = 0; p < 8; p++) {
                uint32_t b0, b1, b2, b3;
                ldsm_x4(b0, b1, b2, b3, vbyte + oV + p * 2304 + s * 32);
                mma16816(O[2 * p],     a0, a1, a2, a3, b0, b1);
                mma16816(O[2 * p + 1], a0, a1, a2, a3, b2, b3);
            }
        }
    }

    // combine l across the two key-half warps of each row band
    if (ci == 0) {
        s_lsum[nh * 128 + rw + gr]     = l0;
        s_lsum[nh * 128 + rw + gr + 8] = l1;
    }
    __syncthreads();

    // epilogue: out = gamma*O/l + x
    const float gm = gamma[0];
    const float li0 = gm / (s_lsum[rw + gr]     + s_lsum[128 + rw + gr]);
    const float li1 = gm / (s_lsum[rw + gr + 8] + s_lsum[128 + rw + gr + 8]);
    const int r0 = j0 + rw + gr;
#pragma unroll
    for (int nb = 0; nb < 16; nb++) {
        int ch = nh * 128 + nb * 8 + ci * 2;
        size_t i0 = ((size_t)(b * 256 + ch)) * 4096 + r0;
        out[i0]            = O[nb][0] * li0 + x[i0];
        out[i0 + 4096]     = O[nb][1] * li0 + x[i0 + 4096];
        out[i0 + 8]        = O[nb][2] * li1 + x[i0 + 8];
        out[i0 + 4096 + 8] = O[nb][3] * li1 + x[i0 + 4096 + 8];
    }
}

// ===========================================================================
extern "C" void kernel_launch(void* const* d_in, const int* in_sizes, int n_in,
                              void* d_out, int out_size)
{
    const float* x     = (const float*)d_in[0];
    const float* wq    = (const float*)d_in[1];
    const float* bq    = (const float*)d_in[2];
    const float* wk    = (const float*)d_in[3];
    const float* bk    = (const float*)d_in[4];
    const float* wv    = (const float*)d_in[5];
    const float* bv    = (const float*)d_in[6];
    const float* gamma = (const float*)d_in[7];
    const float* eps_q = (const float*)d_in[8];
    const float* eps_k = (const float*)d_in[9];
    float* out = (float*)d_out;

    qk_conv_kernel<<<256, 256>>>(x, wq, bq, wk, bk);
    frn_mish_pack_kernel<<<128, 256>>>(eps_q, eps_k);

    cudaFuncSetAttribute(v_gemm_mma_kernel,
                         cudaFuncAttributeMaxDynamicSharedMemorySize, VG_SMEM);
    v_gemm_mma_kernel<<<dim3(32, 4), 512, VG_SMEM>>>(x, wv, bv);

    cudaFuncSetAttribute(attn_mma_kernel,
                         cudaFuncAttributeMaxDynamicSharedMemorySize,
                         ATTN_SMEM_BYTES);
    attn_mma_kernel<<<dim3(32, 4), 512, ATTN_SMEM_BYTES>>>(x, gamma, out);
}

// round 11
// speedup vs baseline: 5.2759x; 1.1854x over previous
#include <cuda_runtime.h>
#include <cuda_fp16.h>
#include <math.h>
#include <stdint.h>

// ---------------------------------------------------------------------------
// B=4, C=256, C16=16, H=W=64, N=4096. Attention: 128 q/CTA, 64-key tiles.
// Q/K tile row stride = 24 halves (48B), V/P stride = 72 halves (144B):
// both give conflict-free LDSM phases (48*r mod 128 and 144*r mod 128 walk
// distinct 16B segments).
// ---------------------------------------------------------------------------

__device__ float g_q[4 * 16 * 4096];             // conv out (b,c16,n) fp32
__device__ float g_k[4 * 16 * 4096];
__device__ __half g_qt[4 * 32 * 128 * 24];       // Q tiles [b][qt][row128][24]
__device__ __half g_kt[4 * 64 * 64 * 24];        // K tiles [b][nt][key64][24]
__device__ __half g_vt[4 * 64 * 256 * 72];       // V tiles [b][nt][ch256][72]

// m16n8k16 f16 MMA, fp32 accum (baseline sm_80 PTX -> HMMA on sm_103)
__device__ __forceinline__ void mma16816(float d[4],
    uint32_t a0, uint32_t a1, uint32_t a2, uint32_t a3,
    uint32_t b0, uint32_t b1)
{
    asm volatile(
        "mma.sync.aligned.m16n8k16.row.col.f32.f16.f16.f32 "
        "{%0,%1,%2,%3}, {%4,%5,%6,%7}, {%8,%9}, {%0,%1,%2,%3};"
        : "+f"(d[0]), "+f"(d[1]), "+f"(d[2]), "+f"(d[3])
        : "r"(a0), "r"(a1), "r"(a2), "r"(a3), "r"(b0), "r"(b1));
}
__device__ __forceinline__ void ldsm_x4(uint32_t& r0, uint32_t& r1,
                                        uint32_t& r2, uint32_t& r3, uint32_t a) {
    asm volatile("ldmatrix.sync.aligned.m8n8.x4.shared.b16 {%0,%1,%2,%3}, [%4];"
                 : "=r"(r0), "=r"(r1), "=r"(r2), "=r"(r3) : "r"(a));
}
__device__ __forceinline__ void ldsm_x4_t(uint32_t& r0, uint32_t& r1,
                                          uint32_t& r2, uint32_t& r3, uint32_t a) {
    asm volatile("ldmatrix.sync.aligned.m8n8.x4.trans.shared.b16 {%0,%1,%2,%3}, [%4];"
                 : "=r"(r0), "=r"(r1), "=r"(r2), "=r"(r3) : "r"(a));
}
__device__ __forceinline__ uint32_t smem_u32(const void* p) {
    uint32_t a;
    asm("{ .reg .u64 t; cvta.to.shared.u64 t, %1; cvt.u32.u64 %0, t; }"
        : "=r"(a) : "l"(p));
    return a;
}
__device__ __forceinline__ void cp_async16(uint32_t sm, const void* g) {
    asm volatile("cp.async.cg.shared.global [%0], [%1], 16;"
                 :: "r"(sm), "l"(g) : "memory");
}
#define CP_COMMIT() asm volatile("cp.async.commit_group;" ::: "memory")
#define CP_WAIT0()  asm volatile("cp.async.wait_group 0;" ::: "memory")
#define BAR4(id) asm volatile("bar.sync %0, 128;" :: "r"(id) : "memory")

// ===========================================================================
// Kernel 1: q = conv1x3(x), k = conv3x1(x)  (raw + bias, fp32). 512 threads.
// ===========================================================================
__global__ __launch_bounds__(512) void qk_conv_kernel(
    const float* __restrict__ x,
    const float* __restrict__ wq, const float* __restrict__ bq,
    const float* __restrict__ wk, const float* __restrict__ bk)
{
    __shared__ float xs[3 * 32 * 66];
    __shared__ float wqs[16 * 32 * 3];
    __shared__ float wks[16 * 32 * 3];

    int b = blockIdx.x >> 6;
    int h = blockIdx.x & 63;
    int t = threadIdx.x;
    int co = t >> 5;        // 0..15
    int wb = t & 31;        // w base

    float qa[2] = {0.f, 0.f};
    float ka[2] = {0.f, 0.f};

    for (int ci0 = 0; ci0 < 256; ci0 += 32) {
        __syncthreads();
        if (t < 96) { xs[t * 66 + 0] = 0.f; xs[t * 66 + 65] = 0.f; }
        for (int idx = t; idx < 3 * 32 * 64; idx += 512) {
            int w = idx & 63;
            int rc = idx >> 6;
            int dh = rc >> 5;
            int ci = rc & 31;
            int hh = h + dh - 1;
            float v = 0.f;
            if (hh >= 0 && hh < 64)
                v = x[((b * 256 + ci0 + ci) * 64 + hh) * 64 + w];
            xs[rc * 66 + 1 + w] = v;
        }
        for (int idx = t; idx < 16 * 32 * 3; idx += 512) {
            int kk = idx % 3;
            int rc = idx / 3;
            int cco = rc >> 5;
            int ci = rc & 31;
            wqs[idx] = wq[(cco * 256 + ci0 + ci) * 3 + kk];
            wks[idx] = wk[(cco * 256 + ci0 + ci) * 3 + kk];
        }
        __syncthreads();

        for (int ci = 0; ci < 32; ci++) {
            float q0 = wqs[(co * 32 + ci) * 3 + 0];
            float q1 = wqs[(co * 32 + ci) * 3 + 1];
            float q2 = wqs[(co * 32 + ci) * 3 + 2];
            float k0 = wks[(co * 32 + ci) * 3 + 0];
            float k1 = wks[(co * 32 + ci) * 3 + 1];
            float k2 = wks[(co * 32 + ci) * 3 + 2];
            const float* x0 = &xs[(0 * 32 + ci) * 66];
            const float* x1 = &xs[(1 * 32 + ci) * 66];
            const float* x2 = &xs[(2 * 32 + ci) * 66];
#pragma unroll
            for (int r = 0; r < 2; r++) {
                int w = wb + 32 * r;
                float xm = x1[w];
                float xc = x1[w + 1];
                float xp = x1[w + 2];
                qa[r] += q0 * xm + q1 * xc + q2 * xp;
                ka[r] += k0 * x0[w + 1] + k1 * xc + k2 * x2[w + 1];
            }
        }
    }
    float bqv = bq[co], bkv = bk[co];
    int base = (b * 16 + co) * 4096 + h * 64;
#pragma unroll
    for (int r = 0; r < 2; r++) {
        int w = wb + 32 * r;
        g_q[base + w] = qa[r] + bqv;
        g_k[base + w] = ka[r] + bkv;
    }
}

// ===========================================================================
// Kernel 2: FRN + Mish, pack f16 Q/K tile images (single hi value, slot c).
// ===========================================================================
__global__ __launch_bounds__(256) void frn_mish_pack_kernel(
    const float* __restrict__ eps_q, const float* __restrict__ eps_k)
{
    __shared__ float red[256];
    __shared__ float sc_s;
    int id = blockIdx.x;                 // 0..127
    int branch = id >> 6;
    int b = (id >> 4) & 3;
    int c = id & 15;
    const float* p = (branch ? g_k : g_q) + (b * 16 + c) * 4096;
    float eps = fabsf(branch ? eps_k[c] : eps_q[c]);
    int t = threadIdx.x;

    float s = 0.f;
    for (int i = t; i < 4096; i += 256) { float v = p[i]; s += v * v; }
    red[t] = s;
    __syncthreads();
    for (int off = 128; off > 0; off >>= 1) {
        if (t < off) red[t] += red[t + off];
        __syncthreads();
    }
    if (t == 0) sc_s = rsqrtf(red[0] / 4096.f + eps);
    __syncthreads();
    float sc = sc_s;
    for (int i = t; i < 4096; i += 256) {
        float v = p[i] * sc;
        float sp = (v > 20.f) ? v : log1pf(expf(v));
        float m = v * tanhf(sp);
        __half hi = __float2half_rn(m);
        if (!branch) {
            int row = i & 127, qt = i >> 7;
            g_qt[((size_t)(b * 32 + qt) * 128 + row) * 24 + c] = hi;
        } else {
            int key = i & 63, ntl = i >> 6;
            g_kt[((size_t)(b * 64 + ntl) * 64 + key) * 24 + c] = hi;
        }
    }
}

// ===========================================================================
// Kernel 3: v = wv @ x + bv via HMMA (f16 inputs, fp32 accum).
// ===========================================================================
#define VG_XOFF (256 * 72)
#define VG_SMEM ((256 * 72 + 64 * 136) * 2)

__global__ __launch_bounds__(512) void v_gemm_mma_kernel(
    const float* __restrict__ x,
    const float* __restrict__ wv, const float* __restrict__ bv)
{
    extern __shared__ __half vsh[];
    __half* Ws = vsh;
    __half* Xs = vsh + VG_XOFF;
    const int b = blockIdx.y, nblk = blockIdx.x, n0 = nblk * 128;
    const int t = threadIdx.x, w = t >> 5, lane = t & 31;
    const int g = lane >> 3, r8 = lane & 7;
    const int cw = w * 16;
    const uint32_t shb = smem_u32(vsh);
    const uint32_t aA = shb + ((cw + (g & 1) * 8 + r8) * 72 + (g >> 1) * 8) * 2;
    const uint32_t aB = shb + VG_XOFF * 2 + ((g & 1) * 8 + r8) * 136 * 2 + (g >> 1) * 16;

    float Acc[16][4];
#pragma unroll
    for (int nb = 0; nb < 16; nb++)
        Acc[nb][0] = Acc[nb][1] = Acc[nb][2] = Acc[nb][3] = 0.f;

    for (int kc = 0; kc < 4; kc++) {
        __syncthreads();
        for (int idx = t; idx < 4096; idx += 512) {
            int row = idx >> 4, col4 = (idx & 15) * 4;
            float4 v = *(const float4*)(wv + row * 256 + kc * 64 + col4);
            uint2 hh;
            __half2 h0 = __floats2half2_rn(v.x, v.y);
            __half2 h1 = __floats2half2_rn(v.z, v.w);
            hh.x = *reinterpret_cast<uint32_t*>(&h0);
            hh.y = *reinterpret_cast<uint32_t*>(&h1);
            *reinterpret_cast<uint2*>(Ws + row * 72 + col4) = hh;
        }
        for (int idx = t; idx < 2048; idx += 512) {
            int row = idx >> 5, col4 = (idx & 31) * 4;
            float4 v = *(const float4*)(x + (size_t)(b * 256 + kc * 64 + row) * 4096 + n0 + col4);
            uint2 hh;
            __half2 h0 = __floats2half2_rn(v.x, v.y);
            __half2 h1 = __floats2half2_rn(v.z, v.w);
            hh.x = *reinterpret_cast<uint32_t*>(&h0);
            hh.y = *reinterpret_cast<uint32_t*>(&h1);
            *reinterpret_cast<uint2*>(Xs + row * 136 + col4) = hh;
        }
        __syncthreads();
#pragma unroll
        for (int s = 0; s < 4; s++) {
            uint32_t a0, a1, a2, a3;
            ldsm_x4(a0, a1, a2, a3, aA + s * 32);
#pragma unroll
            for (int p = 0; p < 8; p++) {
                uint32_t b0, b1, b2, b3;
                ldsm_x4_t(b0, b1, b2, b3, aB + s * (16 * 136 * 2) + p * 32);
                mma16816(Acc[2 * p], a0, a1, a2, a3, b0, b1);
                mma16816(Acc[2 * p + 1], a0, a1, a2, a3, b2, b3);
            }
        }
    }

    const int c0 = cw + (lane >> 2);
    const float bv0 = bv[c0], bv1 = bv[c0 + 8];
#pragma unroll
    for (int nb = 0; nb < 16; nb++) {
        int nl = nb * 8 + (lane & 3) * 2;
        int ntl = nblk * 2 + (nl >> 6);
        int key = nl & 63;
        __half* vb = g_vt + (size_t)(b * 64 + ntl) * 256 * 72;
        __half2 h0 = __floats2half2_rn(Acc[nb][0] + bv0, Acc[nb][1] + bv0);
        __half2 h1 = __floats2half2_rn(Acc[nb][2] + bv1, Acc[nb][3] + bv1);
        *reinterpret_cast<uint32_t*>(vb + (size_t)c0 * 72 + key) =
            *reinterpret_cast<uint32_t*>(&h0);
        *reinterpret_cast<uint32_t*>(vb + (size_t)(c0 + 8) * 72 + key) =
            *reinterpret_cast<uint32_t*>(&h1);
    }
}

// ===========================================================================
// Kernel 4: single-pass online-softmax HMMA flash attention + epilogue.
// 512 threads / 16 warps. Warp w: row band a=w&3 (32 rows), quarter kq=w>>2.
// QK: 32 rows x 16 keys (single f16 step). PV: 32 rows x 64 channels.
// The 4 warps of a row band ({a, a+4, a+8, a+12}) exchange max / share P via
// a 128-thread named barrier (id 1+a); full syncs only rotate cp.async bufs.
// smem(halves): Q[0,3072) K2[3072,6144) V2[6144,43008) P[43008,52224)
// ===========================================================================
#define SM_K(buf) (3072 + (buf) * 1536)
#define SM_V(buf) (6144 + (buf) * 18432)
#define SM_P 43008
#define TOT_HALVES 52224
#define ATTN_SMEM_BYTES (TOT_HALVES * 2 + 1024 * 4)

__global__ __launch_bounds__(512, 1) void attn_mma_kernel(
    const float* __restrict__ x, const float* __restrict__ gamma,
    float* __restrict__ out)
{
    extern __shared__ __half sh[];
    __half* Ps = sh + SM_P;
    float* s_pmax = (float*)(sh + TOT_HALVES);   // [4][128]
    float* s_lsum = s_pmax + 512;                // [4][128]

    const int b  = blockIdx.y;
    const int qt = blockIdx.x;
    const int j0 = qt * 128;
    const int t  = threadIdx.x;
    const int w  = t >> 5, lane = t & 31;
    const int gr = lane >> 2, ci = lane & 3;
    const int g  = lane >> 3, r8 = lane & 7;
    const int a  = w & 3;                        // row band (rows 32a..32a+31)
    const int kq = w >> 2;                       // key quarter / channel quarter
    const int rb = a * 32;
    const int barid = 1 + a;
    const float L2E = 1.44269504f;
    const uint32_t shb = smem_u32(sh);

    // LDSM lane addresses
    const uint32_t aQ = shb + ((rb + (g & 1) * 8 + r8) * 24 + (g >> 1) * 8) * 2; // +m*768
    const uint32_t oK = ((kq * 16 + (g >> 1) * 8 + r8) * 24 + (g & 1) * 8) * 2;
    const uint32_t aP = shb + SM_P * 2 +
        ((rb + (g & 1) * 8 + r8) * 72 + (g >> 1) * 8) * 2;                       // +m*2304+s*32
    const uint32_t oV = ((kq * 64 + (g >> 1) * 8 + r8) * 72 + (g & 1) * 8) * 2;  // +p*2304+s*32

    // prefetch tile 0 (K: 192 f4, V: 2304 f4)
    {
        const float4* kg = (const float4*)(g_kt + (size_t)(b * 64 + 0) * 1536);
        const float4* vg = (const float4*)(g_vt + (size_t)(b * 64 + 0) * 18432);
        uint32_t kd = shb + SM_K(0) * 2;
        uint32_t vd = shb + SM_V(0) * 2;
        for (int i = t; i < 192; i += 512)  cp_async16(kd + i * 16, kg + i);
        for (int i = t; i < 2304; i += 512) cp_async16(vd + i * 16, vg + i);
        CP_COMMIT();
    }
    // Q tile load (384 float4)
    {
        const float4* qg = (const float4*)(g_qt + (size_t)(b * 32 + qt) * 3072);
        float4* qd = (float4*)sh;
        for (int i = t; i < 384; i += 512) qd[i] = qg[i];
    }

    float O[2][8][4];
#pragma unroll
    for (int m = 0; m < 2; m++)
#pragma unroll
        for (int nb = 0; nb < 8; nb++)
            O[m][nb][0] = O[m][nb][1] = O[m][nb][2] = O[m][nb][3] = 0.f;
    float mrun[4] = {-1e30f, -1e30f, -1e30f, -1e30f};
    float lrun[4] = {0.f, 0.f, 0.f, 0.f};
    const int r0 = rb + gr;                      // thread's 4 rows: r0, +8, +16, +24

    for (int ntl = 0; ntl < 64; ntl++) {
        CP_WAIT0();
        __syncthreads();     // tile data arrived + both buffers coherent

        if (ntl + 1 < 64) {  // prefetch next tile into the other buffer
            int nn = ntl + 1, bf = nn & 1;
            const float4* kg = (const float4*)(g_kt + (size_t)(b * 64 + nn) * 1536);
            const float4* vg = (const float4*)(g_vt + (size_t)(b * 64 + nn) * 18432);
            uint32_t kd = shb + SM_K(bf) * 2;
            uint32_t vd = shb + SM_V(bf) * 2;
            for (int i = t; i < 192; i += 512)  cp_async16(kd + i * 16, kg + i);
            for (int i = t; i < 2304; i += 512) cp_async16(vd + i * 16, vg + i);
            CP_COMMIT();
        }

        const uint32_t kbyte = shb + SM_K(ntl & 1) * 2;
        const uint32_t vbyte = shb + SM_V(ntl & 1) * 2;

        // ---- QK: 32 rows x 16 keys, single f16 step ----
        float S[4][4];       // [m*2+n][d]
#pragma unroll
        for (int i = 0; i < 4; i++) S[i][0] = S[i][1] = S[i][2] = S[i][3] = 0.f;
        {
            uint32_t qa0, qa1, qa2, qa3, qb0, qb1, qb2, qb3;
            uint32_t b0, b1, b2, b3;
            ldsm_x4(qa0, qa1, qa2, qa3, aQ);
            ldsm_x4(qb0, qb1, qb2, qb3, aQ + 768);
            ldsm_x4(b0, b1, b2, b3, kbyte + oK);
            mma16816(S[0], qa0, qa1, qa2, qa3, b0, b1);
            mma16816(S[1], qa0, qa1, qa2, qa3, b2, b3);
            mma16816(S[2], qb0, qb1, qb2, qb3, b0, b1);
            mma16816(S[3], qb0, qb1, qb2, qb3, b2, b3);
        }

        // partial row max over this warp's 16 keys (4 rows/thread)
        float pm[4];
        pm[0] = fmaxf(fmaxf(S[0][0], S[0][1]), fmaxf(S[1][0], S[1][1]));
        pm[1] = fmaxf(fmaxf(S[0][2], S[0][3]), fmaxf(S[1][2], S[1][3]));
        pm[2] = fmaxf(fmaxf(S[2][0], S[2][1]), fmaxf(S[3][0], S[3][1]));
        pm[3] = fmaxf(fmaxf(S[2][2], S[2][3]), fmaxf(S[3][2], S[3][3]));
#pragma unroll
        for (int j = 0; j < 4; j++) {
            pm[j] = fmaxf(pm[j], __shfl_xor_sync(0xffffffffu, pm[j], 1));
            pm[j] = fmaxf(pm[j], __shfl_xor_sync(0xffffffffu, pm[j], 2));
        }
        if (ci == 0) {
#pragma unroll
            for (int j = 0; j < 4; j++)
                s_pmax[kq * 128 + r0 + j * 8] = pm[j];
        }
        BAR4(barid);

        // ---- combined max, exp -> P (f16), l update, O rescale ----
        float sc[4], mL[4];
#pragma unroll
        for (int j = 0; j < 4; j++) {
            int r = r0 + j * 8;
            float mn = fmaxf(fmaxf(s_pmax[r], s_pmax[128 + r]),
                             fmaxf(s_pmax[256 + r], s_pmax[384 + r]));
            mn = fmaxf(mrun[j], mn);
            sc[j] = exp2f((mrun[j] - mn) * L2E);
            mrun[j] = mn;
            mL[j] = mn * L2E;
        }
        float tl[4] = {0.f, 0.f, 0.f, 0.f};
#pragma unroll
        for (int m = 0; m < 2; m++) {
#pragma unroll
            for (int n = 0; n < 2; n++) {
                int idx = m * 2 + n;
                float y0 = fmaf(S[idx][0], L2E, -mL[2 * m]);
                float y1 = fmaf(S[idx][1], L2E, -mL[2 * m]);
                float y2 = fmaf(S[idx][2], L2E, -mL[2 * m + 1]);
                float y3 = fmaf(S[idx][3], L2E, -mL[2 * m + 1]);
                __half2 h0 = h2exp2(__floats2half2_rn(y0, y1));
                __half2 h1 = h2exp2(__floats2half2_rn(y2, y3));
                *reinterpret_cast<uint32_t*>(
                    Ps + (rb + 16 * m + gr) * 72 + kq * 16 + n * 8 + ci * 2) =
                    *reinterpret_cast<uint32_t*>(&h0);
                *reinterpret_cast<uint32_t*>(
                    Ps + (rb + 16 * m + gr + 8) * 72 + kq * 16 + n * 8 + ci * 2) =
                    *reinterpret_cast<uint32_t*>(&h1);
                tl[2 * m]     += __low2float(h0) + __high2float(h0);
                tl[2 * m + 1] += __low2float(h1) + __high2float(h1);
            }
        }
#pragma unroll
        for (int j = 0; j < 4; j++) lrun[j] = lrun[j] * sc[j] + tl[j];
#pragma unroll
        for (int m = 0; m < 2; m++)
#pragma unroll
            for (int nb = 0; nb < 8; nb++) {
                O[m][nb][0] *= sc[2 * m]; O[m][nb][1] *= sc[2 * m];
                O[m][nb][2] *= sc[2 * m + 1]; O[m][nb][3] *= sc[2 * m + 1];
            }
        BAR4(barid);         // band's full P (all 4 key quarters) visible

        // ---- PV: 32 rows x 64 channels ----
#pragma unroll
        for (int s = 0; s < 4; s++) {
            uint32_t pa0, pa1, pa2, pa3, pb0, pb1, pb2, pb3;
            ldsm_x4(pa0, pa1, pa2, pa3, aP + s * 32);
            ldsm_x4(pb0, pb1, pb2, pb3, aP + 2304 + s * 32);
#pragma unroll
            for (int p = 0; p < 4; p++) {
                uint32_t b0, b1, b2, b3;
                ldsm_x4(b0, b1, b2, b3, vbyte + oV + p * 2304 + s * 32);
                mma16816(O[0][2 * p],     pa0, pa1, pa2, pa3, b0, b1);
                mma16816(O[0][2 * p + 1], pa0, pa1, pa2, pa3, b2, b3);
                mma16816(O[1][2 * p],     pb0, pb1, pb2, pb3, b0, b1);
                mma16816(O[1][2 * p + 1], pb0, pb1, pb2, pb3, b2, b3);
            }
        }
    }

    // combine l across the 4 key-quarter warps of each row band
#pragma unroll
    for (int j = 0; j < 4; j++) {
        lrun[j] += __shfl_xor_sync(0xffffffffu, lrun[j], 1);
        lrun[j] += __shfl_xor_sync(0xffffffffu, lrun[j], 2);
    }
    if (ci == 0) {
#pragma unroll
        for (int j = 0; j < 4; j++)
            s_lsum[kq * 128 + r0 + j * 8] = lrun[j];
    }
    __syncthreads();

    // epilogue: out = gamma*O/l + x
    const float gm = gamma[0];
    float li[4];
#pragma unroll
    for (int j = 0; j < 4; j++) {
        int r = r0 + j * 8;
        li[j] = gm / (s_lsum[r] + s_lsum[128 + r] + s_lsum[256 + r] + s_lsum[384 + r]);
    }
#pragma unroll
    for (int m = 0; m < 2; m++) {
        const int row = j0 + rb + 16 * m + gr;
#pragma unroll
        for (int nb = 0; nb < 8; nb++) {
            int ch = kq * 64 + nb * 8 + ci * 2;
            size_t i0 = ((size_t)(b * 256 + ch)) * 4096 + row;
            out[i0]            = O[m][nb][0] * li[2 * m] + x[i0];
            out[i0 + 4096]     = O[m][nb][1] * li[2 * m] + x[i0 + 4096];
            out[i0 + 8]        = O[m][nb][2] * li[2 * m + 1] + x[i0 + 8];
            out[i0 + 4096 + 8] = O[m][nb][3] * li[2 * m + 1] + x[i0 + 4096 + 8];
        }
    }
}

// ===========================================================================
extern "C" void kernel_launch(void* const* d_in, const int* in_sizes, int n_in,
                              void* d_out, int out_size)
{
    const float* x     = (const float*)d_in[0];
    const float* wq    = (const float*)d_in[1];
    const float* bq    = (const float*)d_in[2];
    const float* wk    = (const float*)d_in[3];
    const float* bk    = (const float*)d_in[4];
    const float* wv    = (const float*)d_in[5];
    const float* bv    = (const float*)d_in[6];
    const float* gamma = (const float*)d_in[7];
    const float* eps_q = (const float*)d_in[8];
    const float* eps_k = (const float*)d_in[9];
    float* out = (float*)d_out;

    qk_conv_kernel<<<256, 512>>>(x, wq, bq, wk, bk);
    frn_mish_pack_kernel<<<128, 256>>>(eps_q, eps_k);

    cudaFuncSetAttribute(v_gemm_mma_kernel,
                         cudaFuncAttributeMaxDynamicSharedMemorySize, VG_SMEM);
    v_gemm_mma_kernel<<<dim3(32, 4), 512, VG_SMEM>>>(x, wv, bv);

    cudaFuncSetAttribute(attn_mma_kernel,
                         cudaFuncAttributeMaxDynamicSharedMemorySize,
                         ATTN_SMEM_BYTES);
    attn_mma_kernel<<<dim3(32, 4), 512, ATTN_SMEM_BYTES>>>(x, gamma, out);
}

// round 12
// speedup vs baseline: 5.4138x; 1.0261x over previous
#include <cuda_runtime.h>
#include <cuda_fp16.h>
#include <math.h>
#include <stdint.h>

// ---------------------------------------------------------------------------
// B=4, C=256, C16=16, H=W=64, N=4096. Attention: 64 q/CTA (256 CTAs,
// 2 CTAs/SM), 64-key tiles. Q/K tile row stride = 24 halves, V/P stride = 72
// halves: conflict-free LDSM phases.
// ---------------------------------------------------------------------------

__device__ float g_q[4 * 16 * 4096];             // conv out (b,c16,n) fp32
__device__ float g_k[4 * 16 * 4096];
__device__ __half g_qt[4 * 64 * 64 * 24];        // Q tiles [b][qt64][row64][24]
__device__ __half g_kt[4 * 64 * 64 * 24];        // K tiles [b][nt][key64][24]
__device__ __half g_vt[4 * 64 * 256 * 72];       // V tiles [b][nt][ch256][72]

// m16n8k16 f16 MMA, fp32 accum (baseline sm_80 PTX -> HMMA on sm_103)
__device__ __forceinline__ void mma16816(float d[4],
    uint32_t a0, uint32_t a1, uint32_t a2, uint32_t a3,
    uint32_t b0, uint32_t b1)
{
    asm volatile(
        "mma.sync.aligned.m16n8k16.row.col.f32.f16.f16.f32 "
        "{%0,%1,%2,%3}, {%4,%5,%6,%7}, {%8,%9}, {%0,%1,%2,%3};"
        : "+f"(d[0]), "+f"(d[1]), "+f"(d[2]), "+f"(d[3])
        : "r"(a0), "r"(a1), "r"(a2), "r"(a3), "r"(b0), "r"(b1));
}
__device__ __forceinline__ void ldsm_x4(uint32_t& r0, uint32_t& r1,
                                        uint32_t& r2, uint32_t& r3, uint32_t a) {
    asm volatile("ldmatrix.sync.aligned.m8n8.x4.shared.b16 {%0,%1,%2,%3}, [%4];"
                 : "=r"(r0), "=r"(r1), "=r"(r2), "=r"(r3) : "r"(a));
}
__device__ __forceinline__ void ldsm_x4_t(uint32_t& r0, uint32_t& r1,
                                          uint32_t& r2, uint32_t& r3, uint32_t a) {
    asm volatile("ldmatrix.sync.aligned.m8n8.x4.trans.shared.b16 {%0,%1,%2,%3}, [%4];"
                 : "=r"(r0), "=r"(r1), "=r"(r2), "=r"(r3) : "r"(a));
}
__device__ __forceinline__ uint32_t smem_u32(const void* p) {
    uint32_t a;
    asm("{ .reg .u64 t; cvta.to.shared.u64 t, %1; cvt.u32.u64 %0, t; }"
        : "=r"(a) : "l"(p));
    return a;
}
__device__ __forceinline__ void cp_async16(uint32_t sm, const void* g) {
    asm volatile("cp.async.cg.shared.global [%0], [%1], 16;"
                 :: "r"(sm), "l"(g) : "memory");
}
#define CP_COMMIT() asm volatile("cp.async.commit_group;" ::: "memory")
#define CP_WAIT0()  asm volatile("cp.async.wait_group 0;" ::: "memory")
#define BAR4(id) asm volatile("bar.sync %0, 128;" :: "r"(id) : "memory")

// ===========================================================================
// Kernel 1: q = conv1x3(x), k = conv3x1(x)  (raw + bias, fp32). 512 threads.
// ===========================================================================
__global__ __launch_bounds__(512) void qk_conv_kernel(
    const float* __restrict__ x,
    const float* __restrict__ wq, const float* __restrict__ bq,
    const float* __restrict__ wk, const float* __restrict__ bk)
{
    __shared__ float xs[3 * 32 * 66];
    __shared__ float wqs[16 * 32 * 3];
    __shared__ float wks[16 * 32 * 3];

    int b = blockIdx.x >> 6;
    int h = blockIdx.x & 63;
    int t = threadIdx.x;
    int co = t >> 5;        // 0..15
    int wb = t & 31;        // w base

    float qa[2] = {0.f, 0.f};
    float ka[2] = {0.f, 0.f};

    for (int ci0 = 0; ci0 < 256; ci0 += 32) {
        __syncthreads();
        if (t < 96) { xs[t * 66 + 0] = 0.f; xs[t * 66 + 65] = 0.f; }
        for (int idx = t; idx < 3 * 32 * 64; idx += 512) {
            int w = idx & 63;
            int rc = idx >> 6;
            int dh = rc >> 5;
            int ci = rc & 31;
            int hh = h + dh - 1;
            float v = 0.f;
            if (hh >= 0 && hh < 64)
                v = x[((b * 256 + ci0 + ci) * 64 + hh) * 64 + w];
            xs[rc * 66 + 1 + w] = v;
        }
        for (int idx = t; idx < 16 * 32 * 3; idx += 512) {
            int kk = idx % 3;
            int rc = idx / 3;
            int cco = rc >> 5;
            int ci = rc & 31;
            wqs[idx] = wq[(cco * 256 + ci0 + ci) * 3 + kk];
            wks[idx] = wk[(cco * 256 + ci0 + ci) * 3 + kk];
        }
        __syncthreads();

        for (int ci = 0; ci < 32; ci++) {
            float q0 = wqs[(co * 32 + ci) * 3 + 0];
            float q1 = wqs[(co * 32 + ci) * 3 + 1];
            float q2 = wqs[(co * 32 + ci) * 3 + 2];
            float k0 = wks[(co * 32 + ci) * 3 + 0];
            float k1 = wks[(co * 32 + ci) * 3 + 1];
            float k2 = wks[(co * 32 + ci) * 3 + 2];
            const float* x0 = &xs[(0 * 32 + ci) * 66];
            const float* x1 = &xs[(1 * 32 + ci) * 66];
            const float* x2 = &xs[(2 * 32 + ci) * 66];
#pragma unroll
            for (int r = 0; r < 2; r++) {
                int w = wb + 32 * r;
                float xm = x1[w];
                float xc = x1[w + 1];
                float xp = x1[w + 2];
                qa[r] += q0 * xm + q1 * xc + q2 * xp;
                ka[r] += k0 * x0[w + 1] + k1 * xc + k2 * x2[w + 1];
            }
        }
    }
    float bqv = bq[co], bkv = bk[co];
    int base = (b * 16 + co) * 4096 + h * 64;
#pragma unroll
    for (int r = 0; r < 2; r++) {
        int w = wb + 32 * r;
        g_q[base + w] = qa[r] + bqv;
        g_k[base + w] = ka[r] + bkv;
    }
}

// ===========================================================================
// Kernel 2: FRN + Mish, pack f16 Q/K tile images (float4-vectorized).
// ===========================================================================
__global__ __launch_bounds__(256) void frn_mish_pack_kernel(
    const float* __restrict__ eps_q, const float* __restrict__ eps_k)
{
    __shared__ float red[256];
    __shared__ float sc_s;
    int id = blockIdx.x;                 // 0..127
    int branch = id >> 6;
    int b = (id >> 4) & 3;
    int c = id & 15;
    const float* p = (branch ? g_k : g_q) + (b * 16 + c) * 4096;
    float eps = fabsf(branch ? eps_k[c] : eps_q[c]);
    int t = threadIdx.x;

    float s = 0.f;
    for (int i = t * 4; i < 4096; i += 1024) {
        float4 v = *(const float4*)(p + i);
        s += v.x * v.x + v.y * v.y + v.z * v.z + v.w * v.w;
    }
    red[t] = s;
    __syncthreads();
    for (int off = 128; off > 0; off >>= 1) {
        if (t < off) red[t] += red[t + off];
        __syncthreads();
    }
    if (t == 0) sc_s = rsqrtf(red[0] / 4096.f + eps);
    __syncthreads();
    float sc = sc_s;
    for (int i = t * 4; i < 4096; i += 1024) {
        float4 v4 = *(const float4*)(p + i);
        float vv[4] = {v4.x, v4.y, v4.z, v4.w};
#pragma unroll
        for (int e = 0; e < 4; e++) {
            float v = vv[e] * sc;
            float sp = (v > 20.f) ? v : log1pf(expf(v));
            float m = v * tanhf(sp);
            __half hi = __float2half_rn(m);
            int ii = i + e;
            int row = ii & 63, ntl = ii >> 6;
            if (!branch)
                g_qt[((size_t)(b * 64 + ntl) * 64 + row) * 24 + c] = hi;
            else
                g_kt[((size_t)(b * 64 + ntl) * 64 + row) * 24 + c] = hi;
        }
    }
}

// ===========================================================================
// Kernel 3: v = wv @ x + bv via HMMA (f16 inputs, fp32 accum).
// ===========================================================================
#define VG_XOFF (256 * 72)
#define VG_SMEM ((256 * 72 + 64 * 136) * 2)

__global__ __launch_bounds__(512) void v_gemm_mma_kernel(
    const float* __restrict__ x,
    const float* __restrict__ wv, const float* __restrict__ bv)
{
    extern __shared__ __half vsh[];
    __half* Ws = vsh;
    __half* Xs = vsh + VG_XOFF;
    const int b = blockIdx.y, nblk = blockIdx.x, n0 = nblk * 128;
    const int t = threadIdx.x, w = t >> 5, lane = t & 31;
    const int g = lane >> 3, r8 = lane & 7;
    const int cw = w * 16;
    const uint32_t shb = smem_u32(vsh);
    const uint32_t aA = shb + ((cw + (g & 1) * 8 + r8) * 72 + (g >> 1) * 8) * 2;
    const uint32_t aB = shb + VG_XOFF * 2 + ((g & 1) * 8 + r8) * 136 * 2 + (g >> 1) * 16;

    float Acc[16][4];
#pragma unroll
    for (int nb = 0; nb < 16; nb++)
        Acc[nb][0] = Acc[nb][1] = Acc[nb][2] = Acc[nb][3] = 0.f;

    for (int kc = 0; kc < 4; kc++) {
        __syncthreads();
        for (int idx = t; idx < 4096; idx += 512) {
            int row = idx >> 4, col4 = (idx & 15) * 4;
            float4 v = *(const float4*)(wv + row * 256 + kc * 64 + col4);
            uint2 hh;
            __half2 h0 = __floats2half2_rn(v.x, v.y);
            __half2 h1 = __floats2half2_rn(v.z, v.w);
            hh.x = *reinterpret_cast<uint32_t*>(&h0);
            hh.y = *reinterpret_cast<uint32_t*>(&h1);
            *reinterpret_cast<uint2*>(Ws + row * 72 + col4) = hh;
        }
        for (int idx = t; idx < 2048; idx += 512) {
            int row = idx >> 5, col4 = (idx & 31) * 4;
            float4 v = *(const float4*)(x + (size_t)(b * 256 + kc * 64 + row) * 4096 + n0 + col4);
            uint2 hh;
            __half2 h0 = __floats2half2_rn(v.x, v.y);
            __half2 h1 = __floats2half2_rn(v.z, v.w);
            hh.x = *reinterpret_cast<uint32_t*>(&h0);
            hh.y = *reinterpret_cast<uint32_t*>(&h1);
            *reinterpret_cast<uint2*>(Xs + row * 136 + col4) = hh;
        }
        __syncthreads();
#pragma unroll
        for (int s = 0; s < 4; s++) {
            uint32_t a0, a1, a2, a3;
            ldsm_x4(a0, a1, a2, a3, aA + s * 32);
#pragma unroll
            for (int p = 0; p < 8; p++) {
                uint32_t b0, b1, b2, b3;
                ldsm_x4_t(b0, b1, b2, b3, aB + s * (16 * 136 * 2) + p * 32);
                mma16816(Acc[2 * p], a0, a1, a2, a3, b0, b1);
                mma16816(Acc[2 * p + 1], a0, a1, a2, a3, b2, b3);
            }
        }
    }

    const int c0 = cw + (lane >> 2);
    const float bv0 = bv[c0], bv1 = bv[c0 + 8];
#pragma unroll
    for (int nb = 0; nb < 16; nb++) {
        int nl = nb * 8 + (lane & 3) * 2;
        int ntl = nblk * 2 + (nl >> 6);
        int key = nl & 63;
        __half* vb = g_vt + (size_t)(b * 64 + ntl) * 256 * 72;
        __half2 h0 = __floats2half2_rn(Acc[nb][0] + bv0, Acc[nb][1] + bv0);
        __half2 h1 = __floats2half2_rn(Acc[nb][2] + bv1, Acc[nb][3] + bv1);
        *reinterpret_cast<uint32_t*>(vb + (size_t)c0 * 72 + key) =
            *reinterpret_cast<uint32_t*>(&h0);
        *reinterpret_cast<uint32_t*>(vb + (size_t)(c0 + 8) * 72 + key) =
            *reinterpret_cast<uint32_t*>(&h1);
    }
}

// ===========================================================================
// Kernel 4: single-pass online-softmax HMMA flash attention + epilogue.
// 64 queries/CTA, 256 threads / 8 warps, 2 CTAs per SM.
// Warp w: row band a=w&1 (32 rows), quarter kq=w>>1.
// QK: 32 rows x 16 keys. PV: 32 rows x 64 channels.
// The 4 warps of a band exchange max / share P via 128-thread named barrier.
// smem(halves): Q[0,1536) K2[1536,4608) V2[4608,41472) P[41472,46080)
// ===========================================================================
#define SM_K(buf) (1536 + (buf) * 1536)
#define SM_V(buf) (4608 + (buf) * 18432)
#define SM_P 41472
#define TOT_HALVES 46080
#define ATTN_SMEM_BYTES (TOT_HALVES * 2 + 512 * 4)

__global__ __launch_bounds__(256, 2) void attn_mma_kernel(
    const float* __restrict__ x, const float* __restrict__ gamma,
    float* __restrict__ out)
{
    extern __shared__ __half sh[];
    __half* Ps = sh + SM_P;
    float* s_pmax = (float*)(sh + TOT_HALVES);   // [4][64]
    float* s_lsum = s_pmax + 256;                // [4][64]

    const int b  = blockIdx.y;
    const int qt = blockIdx.x;
    const int j0 = qt * 64;
    const int t  = threadIdx.x;
    const int w  = t >> 5, lane = t & 31;
    const int gr = lane >> 2, ci = lane & 3;
    const int g  = lane >> 3, r8 = lane & 7;
    const int a  = w & 1;                        // row band (rows 32a..32a+31)
    const int kq = w >> 1;                       // key quarter / channel quarter
    const int rb = a * 32;
    const int barid = 1 + a;
    const float L2E = 1.44269504f;
    const uint32_t shb = smem_u32(sh);

    // LDSM lane addresses
    const uint32_t aQ = shb + ((rb + (g & 1) * 8 + r8) * 24 + (g >> 1) * 8) * 2; // +m*768
    const uint32_t oK = ((kq * 16 + (g >> 1) * 8 + r8) * 24 + (g & 1) * 8) * 2;
    const uint32_t aP = shb + SM_P * 2 +
        ((rb + (g & 1) * 8 + r8) * 72 + (g >> 1) * 8) * 2;                       // +m*2304+s*32
    const uint32_t oV = ((kq * 64 + (g >> 1) * 8 + r8) * 72 + (g & 1) * 8) * 2;  // +p*2304+s*32

    // prefetch tile 0 (K: 192 f4, V: 2304 f4)
    {
        const float4* kg = (const float4*)(g_kt + (size_t)(b * 64 + 0) * 1536);
        const float4* vg = (const float4*)(g_vt + (size_t)(b * 64 + 0) * 18432);
        uint32_t kd = shb + SM_K(0) * 2;
        uint32_t vd = shb + SM_V(0) * 2;
        for (int i = t; i < 192; i += 256)  cp_async16(kd + i * 16, kg + i);
        for (int i = t; i < 2304; i += 256) cp_async16(vd + i * 16, vg + i);
        CP_COMMIT();
    }
    // Q tile load (192 float4)
    {
        const float4* qg = (const float4*)(g_qt + (size_t)(b * 64 + qt) * 1536);
        float4* qd = (float4*)sh;
        for (int i = t; i < 192; i += 256) qd[i] = qg[i];
    }
    __syncthreads();

    // hoist loop-invariant Q fragments (32 rows x 16 slots per warp)
    uint32_t qf[2][4];
    ldsm_x4(qf[0][0], qf[0][1], qf[0][2], qf[0][3], aQ);
    ldsm_x4(qf[1][0], qf[1][1], qf[1][2], qf[1][3], aQ + 768);

    float O[2][8][4];
#pragma unroll
    for (int m = 0; m < 2; m++)
#pragma unroll
        for (int nb = 0; nb < 8; nb++)
            O[m][nb][0] = O[m][nb][1] = O[m][nb][2] = O[m][nb][3] = 0.f;
    float mrun[4] = {-1e30f, -1e30f, -1e30f, -1e30f};
    float lrun[4] = {0.f, 0.f, 0.f, 0.f};
    const int r0 = rb + gr;                      // thread's 4 rows: r0, +8, +16, +24

    for (int ntl = 0; ntl < 64; ntl++) {
        CP_WAIT0();
        __syncthreads();     // tile data arrived + both buffers coherent

        if (ntl + 1 < 64) {  // prefetch next tile into the other buffer
            int nn = ntl + 1, bf = nn & 1;
            const float4* kg = (const float4*)(g_kt + (size_t)(b * 64 + nn) * 1536);
            const float4* vg = (const float4*)(g_vt + (size_t)(b * 64 + nn) * 18432);
            uint32_t kd = shb + SM_K(bf) * 2;
            uint32_t vd = shb + SM_V(bf) * 2;
            for (int i = t; i < 192; i += 256)  cp_async16(kd + i * 16, kg + i);
            for (int i = t; i < 2304; i += 256) cp_async16(vd + i * 16, vg + i);
            CP_COMMIT();
        }

        const uint32_t kbyte = shb + SM_K(ntl & 1) * 2;
        const uint32_t vbyte = shb + SM_V(ntl & 1) * 2;

        // ---- QK: 32 rows x 16 keys, single f16 step ----
        float S[4][4];       // [m*2+n][d]
#pragma unroll
        for (int i = 0; i < 4; i++) S[i][0] = S[i][1] = S[i][2] = S[i][3] = 0.f;
        {
            uint32_t b0, b1, b2, b3;
            ldsm_x4(b0, b1, b2, b3, kbyte + oK);
            mma16816(S[0], qf[0][0], qf[0][1], qf[0][2], qf[0][3], b0, b1);
            mma16816(S[1], qf[0][0], qf[0][1], qf[0][2], qf[0][3], b2, b3);
            mma16816(S[2], qf[1][0], qf[1][1], qf[1][2], qf[1][3], b0, b1);
            mma16816(S[3], qf[1][0], qf[1][1], qf[1][2], qf[1][3], b2, b3);
        }

        // partial row max over this warp's 16 keys (4 rows/thread)
        float pm[4];
        pm[0] = fmaxf(fmaxf(S[0][0], S[0][1]), fmaxf(S[1][0], S[1][1]));
        pm[1] = fmaxf(fmaxf(S[0][2], S[0][3]), fmaxf(S[1][2], S[1][3]));
        pm[2] = fmaxf(fmaxf(S[2][0], S[2][1]), fmaxf(S[3][0], S[3][1]));
        pm[3] = fmaxf(fmaxf(S[2][2], S[2][3]), fmaxf(S[3][2], S[3][3]));
#pragma unroll
        for (int j = 0; j < 4; j++) {
            pm[j] = fmaxf(pm[j], __shfl_xor_sync(0xffffffffu, pm[j], 1));
            pm[j] = fmaxf(pm[j], __shfl_xor_sync(0xffffffffu, pm[j], 2));
        }
        if (ci == 0) {
#pragma unroll
            for (int j = 0; j < 4; j++)
                s_pmax[kq * 64 + r0 + j * 8] = pm[j];
        }
        BAR4(barid);

        // ---- combined max, exp -> P (f16), l update, O rescale ----
        float sc[4], mL[4];
#pragma unroll
        for (int j = 0; j < 4; j++) {
            int r = r0 + j * 8;
            float mn = fmaxf(fmaxf(s_pmax[r], s_pmax[64 + r]),
                             fmaxf(s_pmax[128 + r], s_pmax[192 + r]));
            mn = fmaxf(mrun[j], mn);
            sc[j] = exp2f((mrun[j] - mn) * L2E);
            mrun[j] = mn;
            mL[j] = mn * L2E;
        }
        float tl[4] = {0.f, 0.f, 0.f, 0.f};
#pragma unroll
        for (int m = 0; m < 2; m++) {
#pragma unroll
            for (int n = 0; n < 2; n++) {
                int idx = m * 2 + n;
                float y0 = fmaf(S[idx][0], L2E, -mL[2 * m]);
                float y1 = fmaf(S[idx][1], L2E, -mL[2 * m]);
                float y2 = fmaf(S[idx][2], L2E, -mL[2 * m + 1]);
                float y3 = fmaf(S[idx][3], L2E, -mL[2 * m + 1]);
                __half2 h0 = h2exp2(__floats2half2_rn(y0, y1));
                __half2 h1 = h2exp2(__floats2half2_rn(y2, y3));
                *reinterpret_cast<uint32_t*>(
                    Ps + (rb + 16 * m + gr) * 72 + kq * 16 + n * 8 + ci * 2) =
                    *reinterpret_cast<uint32_t*>(&h0);
                *reinterpret_cast<uint32_t*>(
                    Ps + (rb + 16 * m + gr + 8) * 72 + kq * 16 + n * 8 + ci * 2) =
                    *reinterpret_cast<uint32_t*>(&h1);
                tl[2 * m]     += __low2float(h0) + __high2float(h0);
                tl[2 * m + 1] += __low2float(h1) + __high2float(h1);
            }
        }
#pragma unroll
        for (int j = 0; j < 4; j++) lrun[j] = lrun[j] * sc[j] + tl[j];

        bool need = (sc[0] != 1.f) | (sc[1] != 1.f) | (sc[2] != 1.f) | (sc[3] != 1.f);
        if (__any_sync(0xffffffffu, need)) {
#pragma unroll
            for (int m = 0; m < 2; m++)
#pragma unroll
                for (int nb = 0; nb < 8; nb++) {
                    O[m][nb][0] *= sc[2 * m]; O[m][nb][1] *= sc[2 * m];
                    O[m][nb][2] *= sc[2 * m + 1]; O[m][nb][3] *= sc[2 * m + 1];
                }
        }
        BAR4(barid);         // band's full P (all 4 key quarters) visible

        // ---- PV: 32 rows x 64 channels ----
#pragma unroll
        for (int s = 0; s < 4; s++) {
            uint32_t pa0, pa1, pa2, pa3, pb0, pb1, pb2, pb3;
            ldsm_x4(pa0, pa1, pa2, pa3, aP + s * 32);
            ldsm_x4(pb0, pb1, pb2, pb3, aP + 2304 + s * 32);
#pragma unroll
            for (int p = 0; p < 4; p++) {
                uint32_t b0, b1, b2, b3;
                ldsm_x4(b0, b1, b2, b3, vbyte + oV + p * 2304 + s * 32);
                mma16816(O[0][2 * p],     pa0, pa1, pa2, pa3, b0, b1);
                mma16816(O[0][2 * p + 1], pa0, pa1, pa2, pa3, b2, b3);
                mma16816(O[1][2 * p],     pb0, pb1, pb2, pb3, b0, b1);
                mma16816(O[1][2 * p + 1], pb0, pb1, pb2, pb3, b2, b3);
            }
        }
    }

    // combine l across the 4 key-quarter warps of each row band
#pragma unroll
    for (int j = 0; j < 4; j++) {
        lrun[j] += __shfl_xor_sync(0xffffffffu, lrun[j], 1);
        lrun[j] += __shfl_xor_sync(0xffffffffu, lrun[j], 2);
    }
    if (ci == 0) {
#pragma unroll
        for (int j = 0; j < 4; j++)
            s_lsum[kq * 64 + r0 + j * 8] = lrun[j];
    }
    __syncthreads();

    // epilogue: out = gamma*O/l + x
    const float gm = gamma[0];
    float li[4];
#pragma unroll
    for (int j = 0; j < 4; j++) {
        int r = r0 + j * 8;
        li[j] = gm / (s_lsum[r] + s_lsum[64 + r] + s_lsum[128 + r] + s_lsum[192 + r]);
    }
#pragma unroll
    for (int m = 0; m < 2; m++) {
        const int row = j0 + rb + 16 * m + gr;
#pragma unroll
        for (int nb = 0; nb < 8; nb++) {
            int ch = kq * 64 + nb * 8 + ci * 2;
            size_t i0 = ((size_t)(b * 256 + ch)) * 4096 + row;
            out[i0]            = O[m][nb][0] * li[2 * m] + x[i0];
            out[i0 + 4096]     = O[m][nb][1] * li[2 * m] + x[i0 + 4096];
            out[i0 + 8]        = O[m][nb][2] * li[2 * m + 1] + x[i0 + 8];
            out[i0 + 4096 + 8] = O[m][nb][3] * li[2 * m + 1] + x[i0 + 4096 + 8];
        }
    }
}

// ===========================================================================
extern "C" void kernel_launch(void* const* d_in, const int* in_sizes, int n_in,
                              void* d_out, int out_size)
{
    const float* x     = (const float*)d_in[0];
    const float* wq    = (const float*)d_in[1];
    const float* bq    = (const float*)d_in[2];
    const float* wk    = (const float*)d_in[3];
    const float* bk    = (const float*)d_in[4];
    const float* wv    = (const float*)d_in[5];
    const float* bv    = (const float*)d_in[6];
    const float* gamma = (const float*)d_in[7];
    const float* eps_q = (const float*)d_in[8];
    const float* eps_k = (const float*)d_in[9];
    float* out = (float*)d_out;

    qk_conv_kernel<<<256, 512>>>(x, wq, bq, wk, bk);
    frn_mish_pack_kernel<<<128, 256>>>(eps_q, eps_k);

    cudaFuncSetAttribute(v_gemm_mma_kernel,
                         cudaFuncAttributeMaxDynamicSharedMemorySize, VG_SMEM);
    v_gemm_mma_kernel<<<dim3(32, 4), 512, VG_SMEM>>>(x, wv, bv);

    cudaFuncSetAttribute(attn_mma_kernel,
                         cudaFuncAttributeMaxDynamicSharedMemorySize,
                         ATTN_SMEM_BYTES);
    attn_mma_kernel<<<dim3(64, 4), 256, ATTN_SMEM_BYTES>>>(x, gamma, out);
}